// round 1
// baseline (speedup 1.0000x reference)
#include <cuda_runtime.h>
#include <math.h>

#define Bn 1024
#define In 512
#define Hn 2048
#define On 512
#define En 8

// ---------------- scratch (device globals; no allocation) ----------------
__device__ int   g_counts[En];
__device__ int   g_tok[En * Bn];          // token id per (expert, slot)
__device__ int   g_pos[Bn * 2];           // per token: e*1024+slot for k=0,1
__device__ float g_wk[Bn * 2];            // per token: renormalized top-2 weights
__device__ float g_h[En * Bn * Hn];       // 64 MB hidden scratch
__device__ float g_y[En * Bn * On];       // 16 MB expert-output scratch

// ---------------- kernel 0: zero counters ----------------
__global__ void zero_counts_kernel() {
    if (threadIdx.x < En) g_counts[threadIdx.x] = 0;
}

// ---------------- kernel 1: gating (1 warp per token) ----------------
__global__ void gate_kernel(const float* __restrict__ x,
                            const float* __restrict__ Wg,
                            const float* __restrict__ bg) {
    int warp = threadIdx.x >> 5, lane = threadIdx.x & 31;
    int b = blockIdx.x * 8 + warp;
    const float* xr = x + (size_t)b * In;

    float acc[En];
#pragma unroll
    for (int e = 0; e < En; e++) acc[e] = 0.f;

    for (int i = lane; i < In; i += 32) {
        float xv = xr[i];
        const float4* w4 = reinterpret_cast<const float4*>(Wg + (size_t)i * En);
        float4 w0 = w4[0], w1 = w4[1];
        acc[0] += xv * w0.x; acc[1] += xv * w0.y;
        acc[2] += xv * w0.z; acc[3] += xv * w0.w;
        acc[4] += xv * w1.x; acc[5] += xv * w1.y;
        acc[6] += xv * w1.z; acc[7] += xv * w1.w;
    }
#pragma unroll
    for (int e = 0; e < En; e++) {
#pragma unroll
        for (int off = 16; off; off >>= 1)
            acc[e] += __shfl_xor_sync(0xffffffffu, acc[e], off);
    }

    if (lane == 0) {
        float lg[En];
        float m = -1e30f;
#pragma unroll
        for (int e = 0; e < En; e++) { lg[e] = acc[e] + bg[e]; m = fmaxf(m, lg[e]); }
        float p[En]; float s = 0.f;
#pragma unroll
        for (int e = 0; e < En; e++) { p[e] = expf(lg[e] - m); s += p[e]; }
#pragma unroll
        for (int e = 0; e < En; e++) p[e] /= s;

        // top-2 with lowest-index-wins on ties (matches jax.lax.top_k)
        int i0 = 0;
#pragma unroll
        for (int e = 1; e < En; e++) if (p[e] > p[i0]) i0 = e;
        int i1 = (i0 == 0) ? 1 : 0;
#pragma unroll
        for (int e = 0; e < En; e++) if (e != i0 && p[e] > p[i1]) i1 = e;

        float sum2 = p[i0] + p[i1];
        float w0 = p[i0] / sum2, w1 = p[i1] / sum2;

        int s0 = atomicAdd(&g_counts[i0], 1);
        g_tok[i0 * Bn + s0] = b;
        g_pos[b * 2 + 0] = i0 * Bn + s0;
        g_wk[b * 2 + 0] = w0;

        int s1 = atomicAdd(&g_counts[i1], 1);
        g_tok[i1 * Bn + s1] = b;
        g_pos[b * 2 + 1] = i1 * Bn + s1;
        g_wk[b * 2 + 1] = w1;
    }
}

// ---------------- kernel 2: grouped GEMM1 (gathered X @ W1[e]) + bias + ReLU ----------------
// tile 128x128, BK=16, 256 threads, 8x8 microtile
__global__ void __launch_bounds__(256) gemm1_kernel(const float* __restrict__ x,
                                                    const float* __restrict__ W1,
                                                    const float* __restrict__ b1) {
    __shared__ float As[16][128];
    __shared__ float Bs[16][128];
    __shared__ int   toks[128];

    int e = blockIdx.z;
    int count = g_counts[e];
    int m0 = blockIdx.y * 128;
    if (m0 >= count) return;
    int n0 = blockIdx.x * 128;
    int tid = threadIdx.x;

    if (tid < 128) {
        int r = m0 + tid;
        toks[tid] = g_tok[e * Bn + (r < count ? r : count - 1)];
    }
    __syncthreads();

    int arow = tid & 127;          // row this thread loads for A
    int akc  = tid >> 7;           // 0/1 -> k-chunk group
    const float* Abase = x + (size_t)toks[arow] * In;
    const float* Bbase = W1 + (size_t)e * In * Hn + n0;

    int tm = tid >> 4, tn = tid & 15;
    float acc[8][8];
#pragma unroll
    for (int i = 0; i < 8; i++)
#pragma unroll
        for (int j = 0; j < 8; j++) acc[i][j] = 0.f;

    for (int kt = 0; kt < In; kt += 16) {
        // A: 128 rows x 16 k, gathered; each thread 2 float4 (transposed store)
#pragma unroll
        for (int jj = 0; jj < 2; jj++) {
            int kc4 = akc + jj * 2;                        // 0..3
            float4 v = *reinterpret_cast<const float4*>(Abase + kt + kc4 * 4);
            As[kc4 * 4 + 0][arow] = v.x;
            As[kc4 * 4 + 1][arow] = v.y;
            As[kc4 * 4 + 2][arow] = v.z;
            As[kc4 * 4 + 3][arow] = v.w;
        }
        // B: 16 rows x 128 cols, coalesced float4
#pragma unroll
        for (int jj = 0; jj < 2; jj++) {
            int f = tid + jj * 256;
            int krow = f >> 5, c4 = f & 31;
            *reinterpret_cast<float4*>(&Bs[krow][c4 * 4]) =
                *reinterpret_cast<const float4*>(Bbase + (size_t)(kt + krow) * Hn + c4 * 4);
        }
        __syncthreads();

#pragma unroll
        for (int kk = 0; kk < 16; kk++) {
            float a[8], bb[8];
            *reinterpret_cast<float4*>(a)     = *reinterpret_cast<float4*>(&As[kk][tm * 8]);
            *reinterpret_cast<float4*>(a + 4) = *reinterpret_cast<float4*>(&As[kk][tm * 8 + 4]);
            // B columns split: [tn*4 .. +3] and [64+tn*4 .. +3] (conflict-free LDS.128)
            *reinterpret_cast<float4*>(bb)     = *reinterpret_cast<float4*>(&Bs[kk][tn * 4]);
            *reinterpret_cast<float4*>(bb + 4) = *reinterpret_cast<float4*>(&Bs[kk][64 + tn * 4]);
#pragma unroll
            for (int i = 0; i < 8; i++)
#pragma unroll
                for (int j = 0; j < 8; j++)
                    acc[i][j] = fmaf(a[i], bb[j], acc[i][j]);
        }
        __syncthreads();
    }

    float bias[8];
#pragma unroll
    for (int j = 0; j < 4; j++) bias[j]     = b1[e * Hn + n0 + tn * 4 + j];
#pragma unroll
    for (int j = 0; j < 4; j++) bias[j + 4] = b1[e * Hn + n0 + 64 + tn * 4 + j];

#pragma unroll
    for (int i = 0; i < 8; i++) {
        int row = m0 + tm * 8 + i;                 // always < Bn; garbage rows harmless
        float* hp = g_h + (size_t)(e * Bn + row) * Hn + n0;
        float4 v0, v1;
        v0.x = fmaxf(acc[i][0] + bias[0], 0.f);
        v0.y = fmaxf(acc[i][1] + bias[1], 0.f);
        v0.z = fmaxf(acc[i][2] + bias[2], 0.f);
        v0.w = fmaxf(acc[i][3] + bias[3], 0.f);
        v1.x = fmaxf(acc[i][4] + bias[4], 0.f);
        v1.y = fmaxf(acc[i][5] + bias[5], 0.f);
        v1.z = fmaxf(acc[i][6] + bias[6], 0.f);
        v1.w = fmaxf(acc[i][7] + bias[7], 0.f);
        *reinterpret_cast<float4*>(hp + tn * 4)      = v0;
        *reinterpret_cast<float4*>(hp + 64 + tn * 4) = v1;
    }
}

// ---------------- kernel 3: grouped GEMM2 (h @ W2[e]) ----------------
// tile 64x64, BK=16, 256 threads, 4x4 microtile
__global__ void __launch_bounds__(256) gemm2_kernel(const float* __restrict__ W2) {
    __shared__ float As[16][68];   // pad 68: 16B-aligned rows, mild STS conflicts only
    __shared__ float Bs[16][64];

    int e = blockIdx.z;
    int count = g_counts[e];
    int m0 = blockIdx.y * 64;
    if (m0 >= count) return;
    int n0 = blockIdx.x * 64;
    int tid = threadIdx.x;

    int arow = tid >> 2, akc = tid & 3;
    const float* Abase = g_h + (size_t)(e * Bn + m0 + arow) * Hn;
    const float* Bbase = W2 + (size_t)e * Hn * On + n0;

    int tm = tid >> 4, tn = tid & 15;
    float acc[4][4];
#pragma unroll
    for (int i = 0; i < 4; i++)
#pragma unroll
        for (int j = 0; j < 4; j++) acc[i][j] = 0.f;

    int bkrow = tid >> 4, bc4 = tid & 15;

    for (int kt = 0; kt < Hn; kt += 16) {
        float4 va = *reinterpret_cast<const float4*>(Abase + kt + akc * 4);
        As[akc * 4 + 0][arow] = va.x;
        As[akc * 4 + 1][arow] = va.y;
        As[akc * 4 + 2][arow] = va.z;
        As[akc * 4 + 3][arow] = va.w;

        *reinterpret_cast<float4*>(&Bs[bkrow][bc4 * 4]) =
            *reinterpret_cast<const float4*>(Bbase + (size_t)(kt + bkrow) * On + bc4 * 4);
        __syncthreads();

#pragma unroll
        for (int kk = 0; kk < 16; kk++) {
            float a[4], bb[4];
            *reinterpret_cast<float4*>(a)  = *reinterpret_cast<float4*>(&As[kk][tm * 4]);
            *reinterpret_cast<float4*>(bb) = *reinterpret_cast<float4*>(&Bs[kk][tn * 4]);
#pragma unroll
            for (int i = 0; i < 4; i++)
#pragma unroll
                for (int j = 0; j < 4; j++)
                    acc[i][j] = fmaf(a[i], bb[j], acc[i][j]);
        }
        __syncthreads();
    }

#pragma unroll
    for (int i = 0; i < 4; i++) {
        int row = m0 + tm * 4 + i;
        float4 v;
        v.x = acc[i][0]; v.y = acc[i][1]; v.z = acc[i][2]; v.w = acc[i][3];
        *reinterpret_cast<float4*>(g_y + (size_t)(e * Bn + row) * On + n0 + tn * 4) = v;
    }
}

// ---------------- kernel 4: weighted combine (+ b2) ----------------
__global__ void combine_kernel(const float* __restrict__ b2, float* __restrict__ out) {
    int idx = blockIdx.x * 256 + threadIdx.x;   // over Bn*On/4
    int b = idx >> 7;                            // On/4 = 128
    int o = (idx & 127) * 4;

    int p0 = g_pos[b * 2 + 0], p1 = g_pos[b * 2 + 1];
    float w0 = g_wk[b * 2 + 0], w1 = g_wk[b * 2 + 1];
    int e0 = p0 >> 10, e1 = p1 >> 10;

    float4 y0 = *reinterpret_cast<const float4*>(g_y + (size_t)p0 * On + o);
    float4 y1 = *reinterpret_cast<const float4*>(g_y + (size_t)p1 * On + o);
    float4 c0 = *reinterpret_cast<const float4*>(b2 + (size_t)e0 * On + o);
    float4 c1 = *reinterpret_cast<const float4*>(b2 + (size_t)e1 * On + o);

    float4 r;
    r.x = w0 * (y0.x + c0.x) + w1 * (y1.x + c1.x);
    r.y = w0 * (y0.y + c0.y) + w1 * (y1.y + c1.y);
    r.z = w0 * (y0.z + c0.z) + w1 * (y1.z + c1.z);
    r.w = w0 * (y0.w + c0.w) + w1 * (y1.w + c1.w);
    *reinterpret_cast<float4*>(out + (size_t)b * On + o) = r;
}

// ---------------- launch ----------------
extern "C" void kernel_launch(void* const* d_in, const int* in_sizes, int n_in,
                              void* d_out, int out_size) {
    const float* x  = (const float*)d_in[0];
    const float* Wg = (const float*)d_in[1];
    const float* bg = (const float*)d_in[2];
    const float* W1 = (const float*)d_in[3];
    const float* b1 = (const float*)d_in[4];
    const float* W2 = (const float*)d_in[5];
    const float* b2 = (const float*)d_in[6];
    float* out = (float*)d_out;

    zero_counts_kernel<<<1, 32>>>();
    gate_kernel<<<Bn / 8, 256>>>(x, Wg, bg);
    gemm1_kernel<<<dim3(Hn / 128, Bn / 128, En), 256>>>(x, W1, b1);
    gemm2_kernel<<<dim3(On / 64, Bn / 64, En), 256>>>(W2);
    combine_kernel<<<(Bn * On / 4) / 256, 256>>>(b2, out);
}

// round 5
// speedup vs baseline: 1.0663x; 1.0663x over previous
#include <cuda_runtime.h>
#include <cuda_bf16.h>
#include <math.h>
#include <stdint.h>

#define Bn 1024
#define In 512
#define Hn 2048
#define On 512
#define En 8

// ---------------- scratch (device globals; zero-init, 16B aligned) ----------------
__device__ __align__(16) int   g_counts[En];
__device__ __align__(16) int   g_tok[En * Bn];
__device__ __align__(16) int   g_pos[Bn * 2];
__device__ __align__(16) float g_wk[Bn * 2];
__device__ __align__(16) float g_h[En * Bn * Hn];   // 64 MB fp32 hidden (R1-proven layout)
__device__ __align__(16) float g_y[En * Bn * On];   // 16 MB fp32 expert outputs

// ---------------- mma helper (m16n8k16 row.col bf16 -> f32) ----------------
__device__ __forceinline__ void mma_bf16(float* c, const uint32_t* a, const uint32_t* b) {
    asm volatile(
        "mma.sync.aligned.m16n8k16.row.col.f32.bf16.bf16.f32 "
        "{%0,%1,%2,%3}, {%4,%5,%6,%7}, {%8,%9}, {%0,%1,%2,%3};"
        : "+f"(c[0]), "+f"(c[1]), "+f"(c[2]), "+f"(c[3])
        : "r"(a[0]), "r"(a[1]), "r"(a[2]), "r"(a[3]), "r"(b[0]), "r"(b[1]));
}

__device__ __forceinline__ void split_bf16(float v, __nv_bfloat16& h, __nv_bfloat16& l) {
    h = __float2bfloat16(v);
    l = __float2bfloat16(v - __bfloat162float(h));
}
__device__ __forceinline__ uint32_t pack2(__nv_bfloat16 a, __nv_bfloat16 b) {
    return ((uint32_t)__bfloat16_as_ushort(b) << 16) | __bfloat16_as_ushort(a);
}

// SMEM tile: 4 planes (Ahi, Alo, Bhi, Blo), each 128 rows x 32 k bf16, pitch 80 B
#define PITCH_B   80
#define TILE_B    10240              // 128 * 80
#define HDR_B     1024               // toks (512B) + bias (512B)
#define GSMEM     (HDR_B + 4 * TILE_B)   // 41984 < 48KB

// ---------------- kernel 0: zero counters ----------------
__global__ void zero_counts_kernel() {
    if (threadIdx.x < En) g_counts[threadIdx.x] = 0;
}

// ---------------- kernel 1: gating (R1-proven, byte identical) ----------------
__global__ void gate_kernel(const float* __restrict__ x,
                            const float* __restrict__ Wg,
                            const float* __restrict__ bg) {
    int warp = threadIdx.x >> 5, lane = threadIdx.x & 31;
    int b = blockIdx.x * 8 + warp;
    const float* xr = x + (size_t)b * In;

    float acc[En];
#pragma unroll
    for (int e = 0; e < En; e++) acc[e] = 0.f;
    for (int i = lane; i < In; i += 32) {
        float xv = xr[i];
        const float4* w4 = reinterpret_cast<const float4*>(Wg + (size_t)i * En);
        float4 w0 = w4[0], w1 = w4[1];
        acc[0] += xv * w0.x; acc[1] += xv * w0.y;
        acc[2] += xv * w0.z; acc[3] += xv * w0.w;
        acc[4] += xv * w1.x; acc[5] += xv * w1.y;
        acc[6] += xv * w1.z; acc[7] += xv * w1.w;
    }
#pragma unroll
    for (int e = 0; e < En; e++) {
#pragma unroll
        for (int off = 16; off; off >>= 1)
            acc[e] += __shfl_xor_sync(0xffffffffu, acc[e], off);
    }
    if (lane == 0) {
        float lg[En]; float m = -1e30f;
#pragma unroll
        for (int e = 0; e < En; e++) { lg[e] = acc[e] + bg[e]; m = fmaxf(m, lg[e]); }
        float p[En]; float s = 0.f;
#pragma unroll
        for (int e = 0; e < En; e++) { p[e] = expf(lg[e] - m); s += p[e]; }
#pragma unroll
        for (int e = 0; e < En; e++) p[e] /= s;
        int i0 = 0;
#pragma unroll
        for (int e = 1; e < En; e++) if (p[e] > p[i0]) i0 = e;
        int i1 = (i0 == 0) ? 1 : 0;
#pragma unroll
        for (int e = 0; e < En; e++) if (e != i0 && p[e] > p[i1]) i1 = e;
        float sum2 = p[i0] + p[i1];
        float w0 = p[i0] / sum2, w1 = p[i1] / sum2;
        int s0 = atomicAdd(&g_counts[i0], 1);
        g_tok[i0 * Bn + s0] = b;
        g_pos[b * 2 + 0] = i0 * Bn + s0;
        g_wk[b * 2 + 0] = w0;
        int s1 = atomicAdd(&g_counts[i1], 1);
        g_tok[i1 * Bn + s1] = b;
        g_pos[b * 2 + 1] = i1 * Bn + s1;
        g_wk[b * 2 + 1] = w1;
    }
}

// ======================= GEMM1: gathered x @ W1[e], +b1, ReLU -> g_h (fp32) =======================
// block: 128 tokens x 128 hidden, K-chunk 32. fp32 loaded directly, split to bf16 hi/lo in staging.
__global__ void __launch_bounds__(256, 1) gemm1_mma(const float* __restrict__ x,
                                                    const float* __restrict__ W1,
                                                    const float* __restrict__ b1) {
    extern __shared__ char smem[];
    int tid = threadIdx.x, wid = tid >> 5, lane = tid & 31;
    int warp_m = wid & 1, warp_n = wid >> 1;

    int e = blockIdx.z;
    int count = g_counts[e];
    int m0 = blockIdx.y * 128;
    if (m0 >= count) return;
    int n0 = blockIdx.x * 128;

    int*   toks   = reinterpret_cast<int*>(smem);
    float* bias_s = reinterpret_cast<float*>(smem + 512);
    if (tid < 128) {
        int r = m0 + tid;
        toks[tid]   = g_tok[e * Bn + (r < count ? r : count - 1)];
        bias_s[tid] = b1[e * Hn + n0 + tid];
    }
    __syncthreads();

    const float* W1e = W1 + (size_t)e * In * Hn;

    float acc[4][4][4];
#pragma unroll
    for (int i = 0; i < 4; i++)
#pragma unroll
        for (int j = 0; j < 4; j++)
#pragma unroll
            for (int k = 0; k < 4; k++) acc[i][j][k] = 0.f;

    char* Ahi = smem + HDR_B;
    char* Alo = Ahi + TILE_B;
    char* Bhi = Alo + TILE_B;
    char* Blo = Bhi + TILE_B;

    const int NC = In / 32;    // 16
    for (int c = 0; c < NC; c++) {
        int kt = c * 32;
        // ---- stage A: 128 rows x 32 k, gathered fp32 -> bf16 hi/lo ----
#pragma unroll
        for (int j = 0; j < 4; j++) {
            int idx = tid + j * 256;            // 0..1023
            int row = idx >> 3, seg = idx & 7;  // seg: 4-float group
            float4 v = *reinterpret_cast<const float4*>(x + (size_t)toks[row] * In + kt + seg * 4);
            __nv_bfloat16 h0, h1, h2, h3, l0, l1, l2, l3;
            split_bf16(v.x, h0, l0); split_bf16(v.y, h1, l1);
            split_bf16(v.z, h2, l2); split_bf16(v.w, h3, l3);
            uint32_t doff = row * PITCH_B + seg * 8;
            *reinterpret_cast<uint2*>(Ahi + doff) = make_uint2(pack2(h0, h1), pack2(h2, h3));
            *reinterpret_cast<uint2*>(Alo + doff) = make_uint2(pack2(l0, l1), pack2(l2, l3));
        }
        // ---- stage B: W1[kt..kt+31][n0..n0+127] fp32, transposed -> [n][k] bf16 hi/lo ----
#pragma unroll
        for (int j = 0; j < 4; j++) {
            int idx = tid + j * 256;
            int kk = idx >> 5, n4 = idx & 31;
            float4 v = *reinterpret_cast<const float4*>(W1e + (size_t)(kt + kk) * Hn + n0 + n4 * 4);
            float f[4] = {v.x, v.y, v.z, v.w};
#pragma unroll
            for (int cc = 0; cc < 4; cc++) {
                __nv_bfloat16 h, l;
                split_bf16(f[cc], h, l);
                uint32_t doff = (n4 * 4 + cc) * PITCH_B + kk * 2;
                *reinterpret_cast<__nv_bfloat16*>(Bhi + doff) = h;
                *reinterpret_cast<__nv_bfloat16*>(Blo + doff) = l;
            }
        }
        __syncthreads();

        // ---- compute: 2 k-steps of m16n8k16, 4x4 tiles, 3 MMAs (hh, hl, lh) ----
#pragma unroll
        for (int ks = 0; ks < 2; ks++) {
            int ko = ks * 32 + (lane & 3) * 4;   // byte offset in k
            uint32_t bh[4][2], bl[4][2];
#pragma unroll
            for (int nt = 0; nt < 4; nt++) {
                int n = warp_n * 32 + nt * 8 + (lane >> 2);
                const char* p = Bhi + n * PITCH_B + ko;
                bh[nt][0] = *(const uint32_t*)p;
                bh[nt][1] = *(const uint32_t*)(p + 16);
                bl[nt][0] = *(const uint32_t*)(p + TILE_B);
                bl[nt][1] = *(const uint32_t*)(p + TILE_B + 16);
            }
#pragma unroll
            for (int mt = 0; mt < 4; mt++) {
                int r = warp_m * 64 + mt * 16 + (lane >> 2);
                const char* p = Ahi + r * PITCH_B + ko;
                uint32_t ah[4] = {*(const uint32_t*)p,
                                  *(const uint32_t*)(p + 8 * PITCH_B),
                                  *(const uint32_t*)(p + 16),
                                  *(const uint32_t*)(p + 8 * PITCH_B + 16)};
                const char* q = p + TILE_B;
                uint32_t al[4] = {*(const uint32_t*)q,
                                  *(const uint32_t*)(q + 8 * PITCH_B),
                                  *(const uint32_t*)(q + 16),
                                  *(const uint32_t*)(q + 8 * PITCH_B + 16)};
#pragma unroll
                for (int nt = 0; nt < 4; nt++) {
                    mma_bf16(acc[mt][nt], ah, bh[nt]);
                    mma_bf16(acc[mt][nt], ah, bl[nt]);
                    mma_bf16(acc[mt][nt], al, bh[nt]);
                }
            }
        }
        __syncthreads();
    }

    // ---- epilogue: +bias, ReLU -> g_h fp32 ----
#pragma unroll
    for (int mt = 0; mt < 4; mt++) {
        int row_l = warp_m * 64 + mt * 16 + (lane >> 2);
#pragma unroll
        for (int nt = 0; nt < 4; nt++) {
            int ncol_l = warp_n * 32 + nt * 8 + (lane & 3) * 2;
            float bb0 = bias_s[ncol_l], bb1 = bias_s[ncol_l + 1];
#pragma unroll
            for (int h = 0; h < 2; h++) {
                int grow = m0 + row_l + h * 8;
                float2 v;
                v.x = fmaxf(acc[mt][nt][h * 2 + 0] + bb0, 0.f);
                v.y = fmaxf(acc[mt][nt][h * 2 + 1] + bb1, 0.f);
                *reinterpret_cast<float2*>(g_h + (size_t)(e * Bn + grow) * Hn + n0 + ncol_l) = v;
            }
        }
    }
}

// ======================= GEMM2: g_h @ W2[e] -> g_y (fp32) =======================
__global__ void __launch_bounds__(256, 1) gemm2_mma(const float* __restrict__ W2) {
    extern __shared__ char smem[];
    int tid = threadIdx.x, wid = tid >> 5, lane = tid & 31;
    int warp_m = wid & 1, warp_n = wid >> 1;

    int e = blockIdx.z;
    int count = g_counts[e];
    int m0 = blockIdx.y * 128;
    if (m0 >= count) return;
    int n0 = blockIdx.x * 128;

    const float* Ae  = g_h + (size_t)(e * Bn + m0) * Hn;
    const float* W2e = W2 + (size_t)e * Hn * On;

    float acc[4][4][4];
#pragma unroll
    for (int i = 0; i < 4; i++)
#pragma unroll
        for (int j = 0; j < 4; j++)
#pragma unroll
            for (int k = 0; k < 4; k++) acc[i][j][k] = 0.f;

    char* Ahi = smem + HDR_B;
    char* Alo = Ahi + TILE_B;
    char* Bhi = Alo + TILE_B;
    char* Blo = Bhi + TILE_B;

    const int NC = Hn / 32;    // 64
    for (int c = 0; c < NC; c++) {
        int kt = c * 32;
#pragma unroll
        for (int j = 0; j < 4; j++) {
            int idx = tid + j * 256;
            int row = idx >> 3, seg = idx & 7;
            float4 v = *reinterpret_cast<const float4*>(Ae + (size_t)row * Hn + kt + seg * 4);
            __nv_bfloat16 h0, h1, h2, h3, l0, l1, l2, l3;
            split_bf16(v.x, h0, l0); split_bf16(v.y, h1, l1);
            split_bf16(v.z, h2, l2); split_bf16(v.w, h3, l3);
            uint32_t doff = row * PITCH_B + seg * 8;
            *reinterpret_cast<uint2*>(Ahi + doff) = make_uint2(pack2(h0, h1), pack2(h2, h3));
            *reinterpret_cast<uint2*>(Alo + doff) = make_uint2(pack2(l0, l1), pack2(l2, l3));
        }
#pragma unroll
        for (int j = 0; j < 4; j++) {
            int idx = tid + j * 256;
            int kk = idx >> 5, n4 = idx & 31;
            float4 v = *reinterpret_cast<const float4*>(W2e + (size_t)(kt + kk) * On + n0 + n4 * 4);
            float f[4] = {v.x, v.y, v.z, v.w};
#pragma unroll
            for (int cc = 0; cc < 4; cc++) {
                __nv_bfloat16 h, l;
                split_bf16(f[cc], h, l);
                uint32_t doff = (n4 * 4 + cc) * PITCH_B + kk * 2;
                *reinterpret_cast<__nv_bfloat16*>(Bhi + doff) = h;
                *reinterpret_cast<__nv_bfloat16*>(Blo + doff) = l;
            }
        }
        __syncthreads();

#pragma unroll
        for (int ks = 0; ks < 2; ks++) {
            int ko = ks * 32 + (lane & 3) * 4;
            uint32_t bh[4][2], bl[4][2];
#pragma unroll
            for (int nt = 0; nt < 4; nt++) {
                int n = warp_n * 32 + nt * 8 + (lane >> 2);
                const char* p = Bhi + n * PITCH_B + ko;
                bh[nt][0] = *(const uint32_t*)p;
                bh[nt][1] = *(const uint32_t*)(p + 16);
                bl[nt][0] = *(const uint32_t*)(p + TILE_B);
                bl[nt][1] = *(const uint32_t*)(p + TILE_B + 16);
            }
#pragma unroll
            for (int mt = 0; mt < 4; mt++) {
                int r = warp_m * 64 + mt * 16 + (lane >> 2);
                const char* p = Ahi + r * PITCH_B + ko;
                uint32_t ah[4] = {*(const uint32_t*)p,
                                  *(const uint32_t*)(p + 8 * PITCH_B),
                                  *(const uint32_t*)(p + 16),
                                  *(const uint32_t*)(p + 8 * PITCH_B + 16)};
                const char* q = p + TILE_B;
                uint32_t al[4] = {*(const uint32_t*)q,
                                  *(const uint32_t*)(q + 8 * PITCH_B),
                                  *(const uint32_t*)(q + 16),
                                  *(const uint32_t*)(q + 8 * PITCH_B + 16)};
#pragma unroll
                for (int nt = 0; nt < 4; nt++) {
                    mma_bf16(acc[mt][nt], ah, bh[nt]);
                    mma_bf16(acc[mt][nt], ah, bl[nt]);
                    mma_bf16(acc[mt][nt], al, bh[nt]);
                }
            }
        }
        __syncthreads();
    }

#pragma unroll
    for (int mt = 0; mt < 4; mt++) {
        int row_l = warp_m * 64 + mt * 16 + (lane >> 2);
#pragma unroll
        for (int nt = 0; nt < 4; nt++) {
            int ncol_l = warp_n * 32 + nt * 8 + (lane & 3) * 2;
#pragma unroll
            for (int h = 0; h < 2; h++) {
                int grow = m0 + row_l + h * 8;
                float2 v = make_float2(acc[mt][nt][h * 2 + 0], acc[mt][nt][h * 2 + 1]);
                *reinterpret_cast<float2*>(g_y + (size_t)(e * Bn + grow) * On + n0 + ncol_l) = v;
            }
        }
    }
}

// ---------------- combine (+ b2) — R1-proven ----------------
__global__ void combine_kernel(const float* __restrict__ b2, float* __restrict__ out) {
    int idx = blockIdx.x * 256 + threadIdx.x;
    int b = idx >> 7;
    int o = (idx & 127) * 4;
    int p0 = g_pos[b * 2 + 0], p1 = g_pos[b * 2 + 1];
    float w0 = g_wk[b * 2 + 0], w1 = g_wk[b * 2 + 1];
    int e0 = p0 >> 10, e1 = p1 >> 10;
    float4 y0 = *reinterpret_cast<const float4*>(g_y + (size_t)p0 * On + o);
    float4 y1 = *reinterpret_cast<const float4*>(g_y + (size_t)p1 * On + o);
    float4 c0 = *reinterpret_cast<const float4*>(b2 + (size_t)e0 * On + o);
    float4 c1 = *reinterpret_cast<const float4*>(b2 + (size_t)e1 * On + o);
    float4 r;
    r.x = w0 * (y0.x + c0.x) + w1 * (y1.x + c1.x);
    r.y = w0 * (y0.y + c0.y) + w1 * (y1.y + c1.y);
    r.z = w0 * (y0.z + c0.z) + w1 * (y1.z + c1.z);
    r.w = w0 * (y0.w + c0.w) + w1 * (y1.w + c1.w);
    *reinterpret_cast<float4*>(out + (size_t)b * On + o) = r;
}

// ---------------- launch ----------------
extern "C" void kernel_launch(void* const* d_in, const int* in_sizes, int n_in,
                              void* d_out, int out_size) {
    const float* x  = (const float*)d_in[0];
    const float* Wg = (const float*)d_in[1];
    const float* bg = (const float*)d_in[2];
    const float* W1 = (const float*)d_in[3];
    const float* b1 = (const float*)d_in[4];
    const float* W2 = (const float*)d_in[5];
    const float* b2 = (const float*)d_in[6];
    float* out = (float*)d_out;

    zero_counts_kernel<<<1, 32>>>();
    gate_kernel<<<Bn / 8, 256>>>(x, Wg, bg);
    gemm1_mma<<<dim3(Hn / 128, Bn / 128, En), 256, GSMEM>>>(x, W1, b1);
    gemm2_mma<<<dim3(On / 128, Bn / 128, En), 256, GSMEM>>>(W2);
    combine_kernel<<<(Bn * On / 4) / 256, 256>>>(b2, out);
}

// round 7
// speedup vs baseline: 1.9267x; 1.8069x over previous
#include <cuda_runtime.h>
#include <cuda_bf16.h>
#include <math.h>
#include <stdint.h>

#define Bn 1024
#define In 512
#define Hn 2048
#define On 512
#define En 8

// ---------------- scratch (device globals; zero-init, 16B aligned) ----------------
__device__ __align__(16) int   g_counts[En];
__device__ __align__(16) int   g_tok[En * Bn];
__device__ __align__(16) int   g_pos[Bn * 2];
__device__ __align__(16) float g_wk[Bn * 2];
__device__ __align__(16) float g_h[En * Bn * Hn];   // 64 MB fp32 hidden (proven layout)
__device__ __align__(16) float g_y[En * Bn * On];   // 16 MB fp32 expert outputs

// ---------------- mma helper (m16n8k16 row.col bf16 -> f32) ----------------
__device__ __forceinline__ void mma_bf16(float* c, const uint32_t* a, const uint32_t* b) {
    asm volatile(
        "mma.sync.aligned.m16n8k16.row.col.f32.bf16.bf16.f32 "
        "{%0,%1,%2,%3}, {%4,%5,%6,%7}, {%8,%9}, {%0,%1,%2,%3};"
        : "+f"(c[0]), "+f"(c[1]), "+f"(c[2]), "+f"(c[3])
        : "r"(a[0]), "r"(a[1]), "r"(a[2]), "r"(a[3]), "r"(b[0]), "r"(b[1]));
}

__device__ __forceinline__ void split_bf16(float v, __nv_bfloat16& h, __nv_bfloat16& l) {
    h = __float2bfloat16(v);
    l = __float2bfloat16(v - __bfloat162float(h));
}
__device__ __forceinline__ uint32_t pack2(__nv_bfloat16 a, __nv_bfloat16 b) {
    return ((uint32_t)__bfloat16_as_ushort(b) << 16) | __bfloat16_as_ushort(a);
}

// SMEM planes: rows x 32 k bf16, pitch 80 B. A plane rows = M-tile; B plane rows = 128 (N-tile).
#define PITCH_B   80
#define BTILE_B   10240              // 128 * 80 (B planes, and A planes when M=128)
#define ATILE64_B 5120               // 64 * 80  (A planes for gemm2, M=64)
#define HDR_B     1024
#define G1SMEM    (HDR_B + 4 * BTILE_B)                  // 41984
#define G2SMEM    (HDR_B + 2 * ATILE64_B + 2 * BTILE_B)  // 31744

// ---------------- kernel 0: zero counters ----------------
__global__ void zero_counts_kernel() {
    if (threadIdx.x < En) g_counts[threadIdx.x] = 0;
}

// ---------------- kernel 1: gating (proven) ----------------
__global__ void gate_kernel(const float* __restrict__ x,
                            const float* __restrict__ Wg,
                            const float* __restrict__ bg) {
    int warp = threadIdx.x >> 5, lane = threadIdx.x & 31;
    int b = blockIdx.x * 8 + warp;
    const float* xr = x + (size_t)b * In;

    float acc[En];
#pragma unroll
    for (int e = 0; e < En; e++) acc[e] = 0.f;
    for (int i = lane; i < In; i += 32) {
        float xv = xr[i];
        const float4* w4 = reinterpret_cast<const float4*>(Wg + (size_t)i * En);
        float4 w0 = w4[0], w1 = w4[1];
        acc[0] += xv * w0.x; acc[1] += xv * w0.y;
        acc[2] += xv * w0.z; acc[3] += xv * w0.w;
        acc[4] += xv * w1.x; acc[5] += xv * w1.y;
        acc[6] += xv * w1.z; acc[7] += xv * w1.w;
    }
#pragma unroll
    for (int e = 0; e < En; e++) {
#pragma unroll
        for (int off = 16; off; off >>= 1)
            acc[e] += __shfl_xor_sync(0xffffffffu, acc[e], off);
    }
    if (lane == 0) {
        float lg[En]; float m = -1e30f;
#pragma unroll
        for (int e = 0; e < En; e++) { lg[e] = acc[e] + bg[e]; m = fmaxf(m, lg[e]); }
        float p[En]; float s = 0.f;
#pragma unroll
        for (int e = 0; e < En; e++) { p[e] = expf(lg[e] - m); s += p[e]; }
#pragma unroll
        for (int e = 0; e < En; e++) p[e] /= s;
        int i0 = 0;
#pragma unroll
        for (int e = 1; e < En; e++) if (p[e] > p[i0]) i0 = e;
        int i1 = (i0 == 0) ? 1 : 0;
#pragma unroll
        for (int e = 0; e < En; e++) if (e != i0 && p[e] > p[i1]) i1 = e;
        float sum2 = p[i0] + p[i1];
        float w0 = p[i0] / sum2, w1 = p[i1] / sum2;
        int s0 = atomicAdd(&g_counts[i0], 1);
        g_tok[i0 * Bn + s0] = b;
        g_pos[b * 2 + 0] = i0 * Bn + s0;
        g_wk[b * 2 + 0] = w0;
        int s1 = atomicAdd(&g_counts[i1], 1);
        g_tok[i1 * Bn + s1] = b;
        g_pos[b * 2 + 1] = i1 * Bn + s1;
        g_wk[b * 2 + 1] = w1;
    }
}

// ---------------- B staging: fp32 W[k][n] -> smem [n][k] bf16 hi/lo, XOR-swizzled ----------------
// 256 threads cover 32 k x 128 n. Thread: ng = n-group of 8 (0..15), kp = k-pair (0..15).
// Element pair (n, k=2kp, 2kp+1) stored as uint32 at n*PITCH + ((4*kp) ^ ((n>>3)&7)*8).
__device__ __forceinline__ void stage_B_f32(const float* __restrict__ W, size_t Nld,
                                            int kt, int n0, int tid,
                                            char* Bhi, char* Blo) {
    int ng = tid & 15, kp = tid >> 4;
    const float* r0 = W + (size_t)(kt + 2 * kp) * Nld + n0 + ng * 8;
    const float* r1 = r0 + Nld;
    float4 a0 = *reinterpret_cast<const float4*>(r0);
    float4 a1 = *reinterpret_cast<const float4*>(r0 + 4);
    float4 b0 = *reinterpret_cast<const float4*>(r1);
    float4 b1 = *reinterpret_cast<const float4*>(r1 + 4);
    float f0[8] = {a0.x, a0.y, a0.z, a0.w, a1.x, a1.y, a1.z, a1.w};
    float f1[8] = {b0.x, b0.y, b0.z, b0.w, b1.x, b1.y, b1.z, b1.w};
    uint32_t sw = (uint32_t)((ng & 7) * 8);
    uint32_t kb = (uint32_t)(4 * kp) ^ sw;
#pragma unroll
    for (int cc = 0; cc < 8; cc++) {
        __nv_bfloat16 h0, l0, h1, l1;
        split_bf16(f0[cc], h0, l0);
        split_bf16(f1[cc], h1, l1);
        uint32_t off = (uint32_t)(ng * 8 + cc) * PITCH_B + kb;
        *reinterpret_cast<uint32_t*>(Bhi + off) = pack2(h0, h1);
        *reinterpret_cast<uint32_t*>(Blo + off) = pack2(l0, l1);
    }
}

// ---------------- compute: MT m-subtiles x 4 n-subtiles, 3 MMAs each ----------------
template <int MT>
__device__ __forceinline__ void compute_tile(const char* Ahi, const char* Bhi,
                                             int lane, int warp_m, int warp_n,
                                             float acc[MT][4][4], int atile) {
#pragma unroll
    for (int ks = 0; ks < 2; ks++) {
        int ko = ks * 32 + (lane & 3) * 4;   // byte offset in k
        uint32_t bh[4][2], bl[4][2];
#pragma unroll
        for (int nt = 0; nt < 4; nt++) {
            int nl = warp_n * 32 + nt * 8 + (lane >> 2);
            uint32_t sw = (uint32_t)(((nl >> 3) & 7) * 8);
            const char* p = Bhi + nl * PITCH_B;
            bh[nt][0] = *(const uint32_t*)(p + (ko ^ sw));
            bh[nt][1] = *(const uint32_t*)(p + ((ko + 16) ^ sw));
            bl[nt][0] = *(const uint32_t*)(p + BTILE_B + (ko ^ sw));
            bl[nt][1] = *(const uint32_t*)(p + BTILE_B + ((ko + 16) ^ sw));
        }
#pragma unroll
        for (int mt = 0; mt < MT; mt++) {
            int r = warp_m * (MT * 16) + mt * 16 + (lane >> 2);
            const char* p = Ahi + r * PITCH_B + ko;
            uint32_t ah[4] = {*(const uint32_t*)p,
                              *(const uint32_t*)(p + 8 * PITCH_B),
                              *(const uint32_t*)(p + 16),
                              *(const uint32_t*)(p + 8 * PITCH_B + 16)};
            const char* q = p + atile;
            uint32_t al[4] = {*(const uint32_t*)q,
                              *(const uint32_t*)(q + 8 * PITCH_B),
                              *(const uint32_t*)(q + 16),
                              *(const uint32_t*)(q + 8 * PITCH_B + 16)};
#pragma unroll
            for (int nt = 0; nt < 4; nt++) {
                mma_bf16(acc[mt][nt], ah, bh[nt]);
                mma_bf16(acc[mt][nt], ah, bl[nt]);
                mma_bf16(acc[mt][nt], al, bh[nt]);
            }
        }
    }
}

// ======================= GEMM1: gathered x @ W1[e], +b1, ReLU -> g_h fp32 =======================
// M=128, N=128, K-chunk 32. Warps: warp_m = wid&1 (64 rows), warp_n = wid>>1 (32 cols).
__global__ void __launch_bounds__(256, 1) gemm1_mma(const float* __restrict__ x,
                                                    const float* __restrict__ W1,
                                                    const float* __restrict__ b1) {
    extern __shared__ char smem[];
    int tid = threadIdx.x, wid = tid >> 5, lane = tid & 31;
    int warp_m = wid & 1, warp_n = wid >> 1;

    int e = blockIdx.z;
    int count = g_counts[e];
    int m0 = blockIdx.y * 128;
    if (m0 >= count) return;
    int n0 = blockIdx.x * 128;

    int*   toks   = reinterpret_cast<int*>(smem);
    float* bias_s = reinterpret_cast<float*>(smem + 512);
    if (tid < 128) {
        int r = m0 + tid;
        toks[tid]   = g_tok[e * Bn + (r < count ? r : count - 1)];
        bias_s[tid] = b1[e * Hn + n0 + tid];
    }
    __syncthreads();

    const float* W1e = W1 + (size_t)e * In * Hn;

    float acc[4][4][4];
#pragma unroll
    for (int i = 0; i < 4; i++)
#pragma unroll
        for (int j = 0; j < 4; j++)
#pragma unroll
            for (int k = 0; k < 4; k++) acc[i][j][k] = 0.f;

    char* Ahi = smem + HDR_B;
    char* Alo = Ahi + BTILE_B;
    char* Bhi = Alo + BTILE_B;
    char* Blo = Bhi + BTILE_B;

    const int NC = In / 32;    // 16
    for (int c = 0; c < NC; c++) {
        int kt = c * 32;
        // stage A: 128 gathered rows x 32 k fp32 -> bf16 hi/lo (proven R5 pattern)
#pragma unroll
        for (int j = 0; j < 4; j++) {
            int idx = tid + j * 256;            // 0..1023
            int row = idx >> 3, seg = idx & 7;  // seg: 4-float group
            float4 v = *reinterpret_cast<const float4*>(x + (size_t)toks[row] * In + kt + seg * 4);
            __nv_bfloat16 h0, h1, h2, h3, l0, l1, l2, l3;
            split_bf16(v.x, h0, l0); split_bf16(v.y, h1, l1);
            split_bf16(v.z, h2, l2); split_bf16(v.w, h3, l3);
            uint32_t doff = (uint32_t)row * PITCH_B + seg * 8;
            *reinterpret_cast<uint2*>(Ahi + doff) = make_uint2(pack2(h0, h1), pack2(h2, h3));
            *reinterpret_cast<uint2*>(Alo + doff) = make_uint2(pack2(l0, l1), pack2(l2, l3));
        }
        stage_B_f32(W1e, Hn, kt, n0, tid, Bhi, Blo);
        __syncthreads();
        compute_tile<4>(Ahi, Bhi, lane, warp_m, warp_n, acc, BTILE_B);
        __syncthreads();
    }

    // epilogue: +bias, ReLU -> g_h fp32 (proven)
#pragma unroll
    for (int mt = 0; mt < 4; mt++) {
        int row_l = warp_m * 64 + mt * 16 + (lane >> 2);
#pragma unroll
        for (int nt = 0; nt < 4; nt++) {
            int ncol_l = warp_n * 32 + nt * 8 + (lane & 3) * 2;
            float bb0 = bias_s[ncol_l], bb1 = bias_s[ncol_l + 1];
#pragma unroll
            for (int h = 0; h < 2; h++) {
                int grow = m0 + row_l + h * 8;
                float2 v;
                v.x = fmaxf(acc[mt][nt][h * 2 + 0] + bb0, 0.f);
                v.y = fmaxf(acc[mt][nt][h * 2 + 1] + bb1, 0.f);
                *reinterpret_cast<float2*>(g_h + (size_t)(e * Bn + grow) * Hn + n0 + ncol_l) = v;
            }
        }
    }
}

// ======================= GEMM2: g_h @ W2[e] -> g_y fp32 =======================
// M=64, N=128 (more active blocks). Warps: warp_m = wid&1 (32 rows), warp_n = wid>>1 (32 cols).
__global__ void __launch_bounds__(256, 1) gemm2_mma(const float* __restrict__ W2) {
    extern __shared__ char smem[];
    int tid = threadIdx.x, wid = tid >> 5, lane = tid & 31;
    int warp_m = wid & 1, warp_n = wid >> 1;

    int e = blockIdx.z;
    int count = g_counts[e];
    int m0 = blockIdx.y * 64;
    if (m0 >= count) return;
    int n0 = blockIdx.x * 128;

    const float* Ae  = g_h + (size_t)(e * Bn + m0) * Hn;
    const float* W2e = W2 + (size_t)e * Hn * On;

    float acc[2][4][4];
#pragma unroll
    for (int i = 0; i < 2; i++)
#pragma unroll
        for (int j = 0; j < 4; j++)
#pragma unroll
            for (int k = 0; k < 4; k++) acc[i][j][k] = 0.f;

    char* Ahi = smem + HDR_B;
    char* Alo = Ahi + ATILE64_B;
    char* Bhi = Alo + ATILE64_B;
    char* Blo = Bhi + BTILE_B;

    const int NC = Hn / 32;    // 64
    for (int c = 0; c < NC; c++) {
        int kt = c * 32;
        // stage A: 64 rows x 32 k fp32 -> bf16 hi/lo
#pragma unroll
        for (int j = 0; j < 2; j++) {
            int idx = tid + j * 256;           // 0..511
            int row = idx >> 3, seg = idx & 7;
            float4 v = *reinterpret_cast<const float4*>(Ae + (size_t)row * Hn + kt + seg * 4);
            __nv_bfloat16 h0, h1, h2, h3, l0, l1, l2, l3;
            split_bf16(v.x, h0, l0); split_bf16(v.y, h1, l1);
            split_bf16(v.z, h2, l2); split_bf16(v.w, h3, l3);
            uint32_t doff = (uint32_t)row * PITCH_B + seg * 8;
            *reinterpret_cast<uint2*>(Ahi + doff) = make_uint2(pack2(h0, h1), pack2(h2, h3));
            *reinterpret_cast<uint2*>(Alo + doff) = make_uint2(pack2(l0, l1), pack2(l2, l3));
        }
        stage_B_f32(W2e, On, kt, n0, tid, Bhi, Blo);
        __syncthreads();
        compute_tile<2>(Ahi, Bhi, lane, warp_m, warp_n, acc, ATILE64_B);
        __syncthreads();
    }

#pragma unroll
    for (int mt = 0; mt < 2; mt++) {
        int row_l = warp_m * 32 + mt * 16 + (lane >> 2);
#pragma unroll
        for (int nt = 0; nt < 4; nt++) {
            int ncol_l = warp_n * 32 + nt * 8 + (lane & 3) * 2;
#pragma unroll
            for (int h = 0; h < 2; h++) {
                int grow = m0 + row_l + h * 8;
                float2 v = make_float2(acc[mt][nt][h * 2 + 0], acc[mt][nt][h * 2 + 1]);
                *reinterpret_cast<float2*>(g_y + (size_t)(e * Bn + grow) * On + n0 + ncol_l) = v;
            }
        }
    }
}

// ---------------- combine (+ b2) — proven ----------------
__global__ void combine_kernel(const float* __restrict__ b2, float* __restrict__ out) {
    int idx = blockIdx.x * 256 + threadIdx.x;
    int b = idx >> 7;
    int o = (idx & 127) * 4;
    int p0 = g_pos[b * 2 + 0], p1 = g_pos[b * 2 + 1];
    float w0 = g_wk[b * 2 + 0], w1 = g_wk[b * 2 + 1];
    int e0 = p0 >> 10, e1 = p1 >> 10;
    float4 y0 = *reinterpret_cast<const float4*>(g_y + (size_t)p0 * On + o);
    float4 y1 = *reinterpret_cast<const float4*>(g_y + (size_t)p1 * On + o);
    float4 c0 = *reinterpret_cast<const float4*>(b2 + (size_t)e0 * On + o);
    float4 c1 = *reinterpret_cast<const float4*>(b2 + (size_t)e1 * On + o);
    float4 r;
    r.x = w0 * (y0.x + c0.x) + w1 * (y1.x + c1.x);
    r.y = w0 * (y0.y + c0.y) + w1 * (y1.y + c1.y);
    r.z = w0 * (y0.z + c0.z) + w1 * (y1.z + c1.z);
    r.w = w0 * (y0.w + c0.w) + w1 * (y1.w + c1.w);
    *reinterpret_cast<float4*>(out + (size_t)b * On + o) = r;
}

// ---------------- launch ----------------
extern "C" void kernel_launch(void* const* d_in, const int* in_sizes, int n_in,
                              void* d_out, int out_size) {
    const float* x  = (const float*)d_in[0];
    const float* Wg = (const float*)d_in[1];
    const float* bg = (const float*)d_in[2];
    const float* W1 = (const float*)d_in[3];
    const float* b1 = (const float*)d_in[4];
    const float* W2 = (const float*)d_in[5];
    const float* b2 = (const float*)d_in[6];
    float* out = (float*)d_out;

    zero_counts_kernel<<<1, 32>>>();
    gate_kernel<<<Bn / 8, 256>>>(x, Wg, bg);
    gemm1_mma<<<dim3(Hn / 128, Bn / 128, En), 256, G1SMEM>>>(x, W1, b1);
    gemm2_mma<<<dim3(On / 128, Bn / 64, En), 256, G2SMEM>>>(W2);
    combine_kernel<<<(Bn * On / 4) / 256, 256>>>(b2, out);
}

// round 8
// speedup vs baseline: 2.3023x; 1.1950x over previous
#include <cuda_runtime.h>
#include <cuda_bf16.h>
#include <math.h>
#include <stdint.h>

#define Bn 1024
#define In 512
#define Hn 2048
#define On 512
#define En 8

// ---------------- scratch (device globals; zero-init, 16B aligned; total ~80MB) ----------------
__device__ __align__(16) int   g_counts[En];
__device__ __align__(16) int   g_tok[En * Bn];
__device__ __align__(16) int   g_pos[Bn * 2];
__device__ __align__(16) float g_wk[Bn * 2];
__device__ __align__(16) __nv_bfloat16 g_hhi[En * Bn * Hn];   // 32 MB
__device__ __align__(16) __nv_bfloat16 g_hlo[En * Bn * Hn];   // 32 MB
__device__ __align__(16) float g_y[En * Bn * On];             // 16 MB

// ---------------- mma helper (m16n8k16 row.col bf16 -> f32) ----------------
__device__ __forceinline__ void mma_bf16(float* c, const uint32_t* a, const uint32_t* b) {
    asm volatile(
        "mma.sync.aligned.m16n8k16.row.col.f32.bf16.bf16.f32 "
        "{%0,%1,%2,%3}, {%4,%5,%6,%7}, {%8,%9}, {%0,%1,%2,%3};"
        : "+f"(c[0]), "+f"(c[1]), "+f"(c[2]), "+f"(c[3])
        : "r"(a[0]), "r"(a[1]), "r"(a[2]), "r"(a[3]), "r"(b[0]), "r"(b[1]));
}

__device__ __forceinline__ void split_bf16(float v, __nv_bfloat16& h, __nv_bfloat16& l) {
    h = __float2bfloat16(v);
    l = __float2bfloat16(v - __bfloat162float(h));
}
__device__ __forceinline__ uint32_t pack2(__nv_bfloat16 a, __nv_bfloat16 b) {
    return ((uint32_t)__bfloat16_as_ushort(b) << 16) | __bfloat16_as_ushort(a);
}

// SMEM geometry: tiles M=64, N=64, K-chunk 32 bf16, pitch 80 B per row.
// One buffer = Ahi|Alo|Bhi|Blo = 4 * (64*80) = 20480 B. Two buffers double-buffered.
#define PITCH_B  80
#define PLANE_B  5120                 // 64 * 80
#define BUF_B    20480                // 4 planes
#define HDR_B    1024
#define GSMEM    (HDR_B + 2 * BUF_B)  // 41984 < 48KB

// ---------------- kernel 0: zero counters ----------------
__global__ void zero_counts_kernel() {
    if (threadIdx.x < En) g_counts[threadIdx.x] = 0;
}

// ---------------- kernel 1: gating (proven) ----------------
__global__ void gate_kernel(const float* __restrict__ x,
                            const float* __restrict__ Wg,
                            const float* __restrict__ bg) {
    int warp = threadIdx.x >> 5, lane = threadIdx.x & 31;
    int b = blockIdx.x * 8 + warp;
    const float* xr = x + (size_t)b * In;

    float acc[En];
#pragma unroll
    for (int e = 0; e < En; e++) acc[e] = 0.f;
    for (int i = lane; i < In; i += 32) {
        float xv = xr[i];
        const float4* w4 = reinterpret_cast<const float4*>(Wg + (size_t)i * En);
        float4 w0 = w4[0], w1 = w4[1];
        acc[0] += xv * w0.x; acc[1] += xv * w0.y;
        acc[2] += xv * w0.z; acc[3] += xv * w0.w;
        acc[4] += xv * w1.x; acc[5] += xv * w1.y;
        acc[6] += xv * w1.z; acc[7] += xv * w1.w;
    }
#pragma unroll
    for (int e = 0; e < En; e++) {
#pragma unroll
        for (int off = 16; off; off >>= 1)
            acc[e] += __shfl_xor_sync(0xffffffffu, acc[e], off);
    }
    if (lane == 0) {
        float lg[En]; float m = -1e30f;
#pragma unroll
        for (int e = 0; e < En; e++) { lg[e] = acc[e] + bg[e]; m = fmaxf(m, lg[e]); }
        float p[En]; float s = 0.f;
#pragma unroll
        for (int e = 0; e < En; e++) { p[e] = expf(lg[e] - m); s += p[e]; }
#pragma unroll
        for (int e = 0; e < En; e++) p[e] /= s;
        int i0 = 0;
#pragma unroll
        for (int e = 1; e < En; e++) if (p[e] > p[i0]) i0 = e;
        int i1 = (i0 == 0) ? 1 : 0;
#pragma unroll
        for (int e = 0; e < En; e++) if (e != i0 && p[e] > p[i1]) i1 = e;
        float sum2 = p[i0] + p[i1];
        float w0 = p[i0] / sum2, w1 = p[i1] / sum2;
        int s0 = atomicAdd(&g_counts[i0], 1);
        g_tok[i0 * Bn + s0] = b;
        g_pos[b * 2 + 0] = i0 * Bn + s0;
        g_wk[b * 2 + 0] = w0;
        int s1 = atomicAdd(&g_counts[i1], 1);
        g_tok[i1 * Bn + s1] = b;
        g_pos[b * 2 + 1] = i1 * Bn + s1;
        g_wk[b * 2 + 1] = w1;
    }
}

// ---------------- B staging: fp32 W[k][n] -> smem [n][k] bf16 hi/lo, XOR swizzle ----------------
// 256 threads cover 32 k x 64 n. nq = tid&15 (n-group of 4), kp = tid>>4 (k-pair 0..15).
__device__ __forceinline__ void stage_B_f32(const float* __restrict__ W, size_t Nld,
                                            int kt, int n0, int tid,
                                            char* Bhi, char* Blo) {
    int nq = tid & 15, kp = tid >> 4;
    const float* r0 = W + (size_t)(kt + 2 * kp) * Nld + n0 + nq * 4;
    const float* r1 = r0 + Nld;
    float4 a = *reinterpret_cast<const float4*>(r0);
    float4 b = *reinterpret_cast<const float4*>(r1);
    float f0[4] = {a.x, a.y, a.z, a.w};
    float f1[4] = {b.x, b.y, b.z, b.w};
#pragma unroll
    for (int cc = 0; cc < 4; cc++) {
        int n = nq * 4 + cc;
        __nv_bfloat16 h0, l0, h1, l1;
        split_bf16(f0[cc], h0, l0);
        split_bf16(f1[cc], h1, l1);
        uint32_t off = (uint32_t)n * PITCH_B + (((uint32_t)(4 * kp)) ^ (uint32_t)(((n >> 3) & 7) * 8));
        *reinterpret_cast<uint32_t*>(Bhi + off) = pack2(h0, h1);
        *reinterpret_cast<uint32_t*>(Blo + off) = pack2(l0, l1);
    }
}

// ---------------- compute: M=64 (warp_m=wid&3, 16 rows), N=64 (warp_n=wid>>2, 32 cols) ----------------
__device__ __forceinline__ void compute_tile(const char* buf, int lane, int warp_m, int warp_n,
                                             float acc[4][4]) {
    const char* Ahi = buf;
    const char* Bhi = buf + 2 * PLANE_B;
#pragma unroll
    for (int ks = 0; ks < 2; ks++) {
        int ko = ks * 32 + (lane & 3) * 4;   // byte offset in k
        uint32_t bh[4][2], bl[4][2];
#pragma unroll
        for (int nt = 0; nt < 4; nt++) {
            int nl = warp_n * 32 + nt * 8 + (lane >> 2);
            uint32_t sw = (uint32_t)(((nl >> 3) & 7) * 8);
            const char* p = Bhi + nl * PITCH_B;
            bh[nt][0] = *(const uint32_t*)(p + (ko ^ sw));
            bh[nt][1] = *(const uint32_t*)(p + ((ko + 16) ^ sw));
            bl[nt][0] = *(const uint32_t*)(p + PLANE_B + (ko ^ sw));
            bl[nt][1] = *(const uint32_t*)(p + PLANE_B + ((ko + 16) ^ sw));
        }
        int r = warp_m * 16 + (lane >> 2);
        const char* p = Ahi + r * PITCH_B + ko;
        uint32_t ah[4] = {*(const uint32_t*)p,
                          *(const uint32_t*)(p + 8 * PITCH_B),
                          *(const uint32_t*)(p + 16),
                          *(const uint32_t*)(p + 8 * PITCH_B + 16)};
        const char* q = p + PLANE_B;
        uint32_t al[4] = {*(const uint32_t*)q,
                          *(const uint32_t*)(q + 8 * PITCH_B),
                          *(const uint32_t*)(q + 16),
                          *(const uint32_t*)(q + 8 * PITCH_B + 16)};
#pragma unroll
        for (int nt = 0; nt < 4; nt++) {
            mma_bf16(acc[nt], ah, bh[nt]);
            mma_bf16(acc[nt], ah, bl[nt]);
            mma_bf16(acc[nt], al, bh[nt]);
        }
    }
}

// ======================= GEMM1: gathered x @ W1[e], +b1, ReLU -> g_hhi/g_hlo =======================
__global__ void __launch_bounds__(256, 2) gemm1_mma(const float* __restrict__ x,
                                                    const float* __restrict__ W1,
                                                    const float* __restrict__ b1) {
    extern __shared__ char smem[];
    int tid = threadIdx.x, wid = tid >> 5, lane = tid & 31;
    int warp_m = wid & 3, warp_n = wid >> 2;

    int e = blockIdx.z;
    int count = g_counts[e];
    int m0 = blockIdx.y * 64;
    if (m0 >= count) return;
    int n0 = blockIdx.x * 64;

    int*   toks   = reinterpret_cast<int*>(smem);
    float* bias_s = reinterpret_cast<float*>(smem + 256);
    if (tid < 64) {
        int r = m0 + tid;
        toks[tid]   = g_tok[e * Bn + (r < count ? r : count - 1)];
        bias_s[tid] = b1[e * Hn + n0 + tid];
    }
    __syncthreads();

    const float* W1e = W1 + (size_t)e * In * Hn;

    float acc[4][4];
#pragma unroll
    for (int j = 0; j < 4; j++)
#pragma unroll
        for (int k = 0; k < 4; k++) acc[j][k] = 0.f;

    // fill(buf, kt): A = 64 gathered x rows x 32 k (fp32 -> hi/lo), B = W1 chunk
    auto fill = [&](char* buf, int kt) {
        char* Ahi = buf; char* Alo = buf + PLANE_B;
#pragma unroll
        for (int j = 0; j < 2; j++) {
            int idx = tid + j * 256;           // 0..511
            int row = idx >> 3, seg = idx & 7;
            float4 v = *reinterpret_cast<const float4*>(x + (size_t)toks[row] * In + kt + seg * 4);
            __nv_bfloat16 h0, h1, h2, h3, l0, l1, l2, l3;
            split_bf16(v.x, h0, l0); split_bf16(v.y, h1, l1);
            split_bf16(v.z, h2, l2); split_bf16(v.w, h3, l3);
            uint32_t doff = (uint32_t)row * PITCH_B + seg * 8;
            *reinterpret_cast<uint2*>(Ahi + doff) = make_uint2(pack2(h0, h1), pack2(h2, h3));
            *reinterpret_cast<uint2*>(Alo + doff) = make_uint2(pack2(l0, l1), pack2(l2, l3));
        }
        stage_B_f32(W1e, Hn, kt, n0, tid, buf + 2 * PLANE_B, buf + 3 * PLANE_B);
    };

    char* buf0 = smem + HDR_B;
    char* buf1 = buf0 + BUF_B;

    const int NC = In / 32;    // 16
    fill(buf0, 0);
    __syncthreads();
    for (int c = 0; c < NC; c++) {
        char* cur = (c & 1) ? buf1 : buf0;
        char* nxt = (c & 1) ? buf0 : buf1;
        if (c + 1 < NC) fill(nxt, (c + 1) * 32);
        compute_tile(cur, lane, warp_m, warp_n, acc);
        __syncthreads();
    }

    // epilogue: +bias, ReLU, split -> g_hhi/g_hlo
#pragma unroll
    for (int nt = 0; nt < 4; nt++) {
        int ncol_l = warp_n * 32 + nt * 8 + (lane & 3) * 2;
        float bb0 = bias_s[ncol_l], bb1 = bias_s[ncol_l + 1];
#pragma unroll
        for (int h = 0; h < 2; h++) {
            int grow = m0 + warp_m * 16 + (lane >> 2) + h * 8;
            float v0 = fmaxf(acc[nt][h * 2 + 0] + bb0, 0.f);
            float v1 = fmaxf(acc[nt][h * 2 + 1] + bb1, 0.f);
            __nv_bfloat16 h0, h1, l0, l1;
            split_bf16(v0, h0, l0); split_bf16(v1, h1, l1);
            size_t off = (size_t)(e * Bn + grow) * Hn + n0 + ncol_l;
            *reinterpret_cast<uint32_t*>(g_hhi + off) = pack2(h0, h1);
            *reinterpret_cast<uint32_t*>(g_hlo + off) = pack2(l0, l1);
        }
    }
}

// ======================= GEMM2: h(bf16 hi/lo) @ W2[e] -> g_y fp32 =======================
__global__ void __launch_bounds__(256, 2) gemm2_mma(const float* __restrict__ W2) {
    extern __shared__ char smem[];
    int tid = threadIdx.x, wid = tid >> 5, lane = tid & 31;
    int warp_m = wid & 3, warp_n = wid >> 2;

    int e = blockIdx.z;
    int count = g_counts[e];
    int m0 = blockIdx.y * 64;
    if (m0 >= count) return;
    int n0 = blockIdx.x * 64;

    const __nv_bfloat16* Ahg = g_hhi + (size_t)(e * Bn + m0) * Hn;
    const __nv_bfloat16* Alg = g_hlo + (size_t)(e * Bn + m0) * Hn;
    const float* W2e = W2 + (size_t)e * Hn * On;

    float acc[4][4];
#pragma unroll
    for (int j = 0; j < 4; j++)
#pragma unroll
        for (int k = 0; k < 4; k++) acc[j][k] = 0.f;

    // fill(buf, kt): A = direct bf16 copies, B = W2 chunk converted
    auto fill = [&](char* buf, int kt) {
        int row = tid >> 2, seg = tid & 3;
        size_t src = (size_t)row * Hn + kt + seg * 8;
        uint32_t doff = (uint32_t)row * PITCH_B + seg * 16;
        *reinterpret_cast<uint4*>(buf + doff)           = *reinterpret_cast<const uint4*>(Ahg + src);
        *reinterpret_cast<uint4*>(buf + PLANE_B + doff) = *reinterpret_cast<const uint4*>(Alg + src);
        stage_B_f32(W2e, On, kt, n0, tid, buf + 2 * PLANE_B, buf + 3 * PLANE_B);
    };

    char* buf0 = smem + HDR_B;
    char* buf1 = buf0 + BUF_B;

    const int NC = Hn / 32;    // 64
    fill(buf0, 0);
    __syncthreads();
    for (int c = 0; c < NC; c++) {
        char* cur = (c & 1) ? buf1 : buf0;
        char* nxt = (c & 1) ? buf0 : buf1;
        if (c + 1 < NC) fill(nxt, (c + 1) * 32);
        compute_tile(cur, lane, warp_m, warp_n, acc);
        __syncthreads();
    }

#pragma unroll
    for (int nt = 0; nt < 4; nt++) {
        int ncol_l = warp_n * 32 + nt * 8 + (lane & 3) * 2;
#pragma unroll
        for (int h = 0; h < 2; h++) {
            int grow = m0 + warp_m * 16 + (lane >> 2) + h * 8;
            float2 v = make_float2(acc[nt][h * 2 + 0], acc[nt][h * 2 + 1]);
            *reinterpret_cast<float2*>(g_y + (size_t)(e * Bn + grow) * On + n0 + ncol_l) = v;
        }
    }
}

// ---------------- combine (+ b2) — proven ----------------
__global__ void combine_kernel(const float* __restrict__ b2, float* __restrict__ out) {
    int idx = blockIdx.x * 256 + threadIdx.x;
    int b = idx >> 7;
    int o = (idx & 127) * 4;
    int p0 = g_pos[b * 2 + 0], p1 = g_pos[b * 2 + 1];
    float w0 = g_wk[b * 2 + 0], w1 = g_wk[b * 2 + 1];
    int e0 = p0 >> 10, e1 = p1 >> 10;
    float4 y0 = *reinterpret_cast<const float4*>(g_y + (size_t)p0 * On + o);
    float4 y1 = *reinterpret_cast<const float4*>(g_y + (size_t)p1 * On + o);
    float4 c0 = *reinterpret_cast<const float4*>(b2 + (size_t)e0 * On + o);
    float4 c1 = *reinterpret_cast<const float4*>(b2 + (size_t)e1 * On + o);
    float4 r;
    r.x = w0 * (y0.x + c0.x) + w1 * (y1.x + c1.x);
    r.y = w0 * (y0.y + c0.y) + w1 * (y1.y + c1.y);
    r.z = w0 * (y0.z + c0.z) + w1 * (y1.z + c1.z);
    r.w = w0 * (y0.w + c0.w) + w1 * (y1.w + c1.w);
    *reinterpret_cast<float4*>(out + (size_t)b * On + o) = r;
}

// ---------------- launch ----------------
extern "C" void kernel_launch(void* const* d_in, const int* in_sizes, int n_in,
                              void* d_out, int out_size) {
    const float* x  = (const float*)d_in[0];
    const float* Wg = (const float*)d_in[1];
    const float* bg = (const float*)d_in[2];
    const float* W1 = (const float*)d_in[3];
    const float* b1 = (const float*)d_in[4];
    const float* W2 = (const float*)d_in[5];
    const float* b2 = (const float*)d_in[6];
    float* out = (float*)d_out;

    zero_counts_kernel<<<1, 32>>>();
    gate_kernel<<<Bn / 8, 256>>>(x, Wg, bg);
    gemm1_mma<<<dim3(Hn / 64, Bn / 64, En), 256, GSMEM>>>(x, W1, b1);
    gemm2_mma<<<dim3(On / 64, Bn / 64, En), 256, GSMEM>>>(W2);
    combine_kernel<<<(Bn * On / 4) / 256, 256>>>(b2, out);
}

// round 9
// speedup vs baseline: 2.3056x; 1.0014x over previous
#include <cuda_runtime.h>
#include <cuda_bf16.h>
#include <math.h>
#include <stdint.h>

#define Bn 1024
#define In 512
#define Hn 2048
#define On 512
#define En 8

// ---------------- scratch (device globals; zero-init, 16B aligned; ~80MB proven budget) ----------------
__device__ __align__(16) int   g_counts[En];
__device__ __align__(16) int   g_tok[En * Bn];
__device__ __align__(16) int   g_pos[Bn * 2];
__device__ __align__(16) float g_wk[Bn * 2];
__device__ __align__(16) __nv_bfloat16 g_hhi[En * Bn * Hn];   // 32 MB
__device__ __align__(16) __nv_bfloat16 g_hlo[En * Bn * Hn];   // 32 MB
__device__ __align__(16) float g_y[En * Bn * On];             // 16 MB

// ---------------- mma helper (m16n8k16 row.col bf16 -> f32) ----------------
__device__ __forceinline__ void mma_bf16(float* c, const uint32_t* a, const uint32_t* b) {
    asm volatile(
        "mma.sync.aligned.m16n8k16.row.col.f32.bf16.bf16.f32 "
        "{%0,%1,%2,%3}, {%4,%5,%6,%7}, {%8,%9}, {%0,%1,%2,%3};"
        : "+f"(c[0]), "+f"(c[1]), "+f"(c[2]), "+f"(c[3])
        : "r"(a[0]), "r"(a[1]), "r"(a[2]), "r"(a[3]), "r"(b[0]), "r"(b[1]));
}

__device__ __forceinline__ void split_bf16(float v, __nv_bfloat16& h, __nv_bfloat16& l) {
    h = __float2bfloat16(v);
    l = __float2bfloat16(v - __bfloat162float(h));
}
__device__ __forceinline__ uint32_t pack2(__nv_bfloat16 a, __nv_bfloat16 b) {
    return ((uint32_t)__bfloat16_as_ushort(b) << 16) | __bfloat16_as_ushort(a);
}

// ---------------- pad-free swizzled smem plane ----------------
// plane: rows x 32 k bf16 = 64 B/row = 4 chunks of 16 B.
// phys(r, chunk c, inner) = r*64 + ((c ^ ((r>>1)&3)) * 16) + inner
// A planes: 128 rows (8192 B). B planes: 64 rows (4096 B).
#define PLANE_A  8192
#define PLANE_Bp 4096
#define BUF_B    (2 * PLANE_A + 2 * PLANE_Bp)   // 24576: Ahi|Alo|Bhi|Blo
#define GSMEM    (2 * BUF_B)                    // 49152 = 48KB exactly (no opt-in)
#define SWZ_R(r) (((r) >> 1) & 3)

// ---------------- kernel 0: zero counters ----------------
__global__ void zero_counts_kernel() {
    if (threadIdx.x < En) g_counts[threadIdx.x] = 0;
}

// ---------------- kernel 1: gating (proven) ----------------
__global__ void gate_kernel(const float* __restrict__ x,
                            const float* __restrict__ Wg,
                            const float* __restrict__ bg) {
    int warp = threadIdx.x >> 5, lane = threadIdx.x & 31;
    int b = blockIdx.x * 8 + warp;
    const float* xr = x + (size_t)b * In;

    float acc[En];
#pragma unroll
    for (int e = 0; e < En; e++) acc[e] = 0.f;
    for (int i = lane; i < In; i += 32) {
        float xv = xr[i];
        const float4* w4 = reinterpret_cast<const float4*>(Wg + (size_t)i * En);
        float4 w0 = w4[0], w1 = w4[1];
        acc[0] += xv * w0.x; acc[1] += xv * w0.y;
        acc[2] += xv * w0.z; acc[3] += xv * w0.w;
        acc[4] += xv * w1.x; acc[5] += xv * w1.y;
        acc[6] += xv * w1.z; acc[7] += xv * w1.w;
    }
#pragma unroll
    for (int e = 0; e < En; e++) {
#pragma unroll
        for (int off = 16; off; off >>= 1)
            acc[e] += __shfl_xor_sync(0xffffffffu, acc[e], off);
    }
    if (lane == 0) {
        float lg[En]; float m = -1e30f;
#pragma unroll
        for (int e = 0; e < En; e++) { lg[e] = acc[e] + bg[e]; m = fmaxf(m, lg[e]); }
        float p[En]; float s = 0.f;
#pragma unroll
        for (int e = 0; e < En; e++) { p[e] = expf(lg[e] - m); s += p[e]; }
#pragma unroll
        for (int e = 0; e < En; e++) p[e] /= s;
        int i0 = 0;
#pragma unroll
        for (int e = 1; e < En; e++) if (p[e] > p[i0]) i0 = e;
        int i1 = (i0 == 0) ? 1 : 0;
#pragma unroll
        for (int e = 0; e < En; e++) if (e != i0 && p[e] > p[i1]) i1 = e;
        float sum2 = p[i0] + p[i1];
        float w0 = p[i0] / sum2, w1 = p[i1] / sum2;
        int s0 = atomicAdd(&g_counts[i0], 1);
        g_tok[i0 * Bn + s0] = b;
        g_pos[b * 2 + 0] = i0 * Bn + s0;
        g_wk[b * 2 + 0] = w0;
        int s1 = atomicAdd(&g_counts[i1], 1);
        g_tok[i1 * Bn + s1] = b;
        g_pos[b * 2 + 1] = i1 * Bn + s1;
        g_wk[b * 2 + 1] = w1;
    }
}

// ---------------- B staging: fp32 W[k][n] -> smem [n][k] bf16 hi/lo (swizzled) ----------------
// 256 threads: n = tid&63, kg = tid>>6 (chunk, 8 k each). 8 strided scalar loads, 2 STS.128.
__device__ __forceinline__ void stage_B_f32(const float* __restrict__ W, size_t Nld,
                                            int kt, int n0, int tid,
                                            char* Bhi, char* Blo) {
    int n = tid & 63, kg = tid >> 6;
    const float* src = W + (size_t)(kt + kg * 8) * Nld + n0 + n;
    float f[8];
#pragma unroll
    for (int j = 0; j < 8; j++) f[j] = src[(size_t)j * Nld];
    uint32_t hi[4], lo[4];
#pragma unroll
    for (int j = 0; j < 4; j++) {
        __nv_bfloat16 h0, l0, h1, l1;
        split_bf16(f[2 * j], h0, l0);
        split_bf16(f[2 * j + 1], h1, l1);
        hi[j] = pack2(h0, h1);
        lo[j] = pack2(l0, l1);
    }
    uint32_t dst = (uint32_t)n * 64 + (uint32_t)((kg ^ SWZ_R(n)) * 16);
    *reinterpret_cast<uint4*>(Bhi + dst) = make_uint4(hi[0], hi[1], hi[2], hi[3]);
    *reinterpret_cast<uint4*>(Blo + dst) = make_uint4(lo[0], lo[1], lo[2], lo[3]);
}

// ---------------- compute: M=128 (warp_m=wid&3, 2 mt of 16 rows), N=64 (warp_n=wid>>2, 4 nt) ----------------
__device__ __forceinline__ void compute_tile(const char* buf, int lane, int warp_m, int warp_n,
                                             float acc[2][4][4]) {
    const char* Ahi = buf;
    const char* Alo = buf + PLANE_A;
    const char* Bhi = buf + 2 * PLANE_A;
    const char* Blo = Bhi + PLANE_Bp;
    int inner = (lane & 3) * 4;
#pragma unroll
    for (int ks = 0; ks < 2; ks++) {
        uint32_t bh[4][2], bl[4][2];
#pragma unroll
        for (int nt = 0; nt < 4; nt++) {
            int nl = warp_n * 32 + nt * 8 + (lane >> 2);
            int sw = SWZ_R(nl);
            uint32_t base = (uint32_t)nl * 64 + inner;
            uint32_t o0 = base + (uint32_t)(((2 * ks) ^ sw) * 16);
            uint32_t o1 = base + (uint32_t)(((2 * ks + 1) ^ sw) * 16);
            bh[nt][0] = *(const uint32_t*)(Bhi + o0);
            bh[nt][1] = *(const uint32_t*)(Bhi + o1);
            bl[nt][0] = *(const uint32_t*)(Blo + o0);
            bl[nt][1] = *(const uint32_t*)(Blo + o1);
        }
#pragma unroll
        for (int mt = 0; mt < 2; mt++) {
            int r0 = warp_m * 32 + mt * 16 + (lane >> 2);
            int r1 = r0 + 8;
            int s0 = SWZ_R(r0), s1 = SWZ_R(r1);
            uint32_t b0 = (uint32_t)r0 * 64 + inner;
            uint32_t b1 = (uint32_t)r1 * 64 + inner;
            uint32_t c00 = b0 + (uint32_t)(((2 * ks) ^ s0) * 16);
            uint32_t c10 = b1 + (uint32_t)(((2 * ks) ^ s1) * 16);
            uint32_t c01 = b0 + (uint32_t)(((2 * ks + 1) ^ s0) * 16);
            uint32_t c11 = b1 + (uint32_t)(((2 * ks + 1) ^ s1) * 16);
            uint32_t ah[4] = {*(const uint32_t*)(Ahi + c00), *(const uint32_t*)(Ahi + c10),
                              *(const uint32_t*)(Ahi + c01), *(const uint32_t*)(Ahi + c11)};
            uint32_t al[4] = {*(const uint32_t*)(Alo + c00), *(const uint32_t*)(Alo + c10),
                              *(const uint32_t*)(Alo + c01), *(const uint32_t*)(Alo + c11)};
#pragma unroll
            for (int nt = 0; nt < 4; nt++) {
                mma_bf16(acc[mt][nt], ah, bh[nt]);
                mma_bf16(acc[mt][nt], ah, bl[nt]);
                mma_bf16(acc[mt][nt], al, bh[nt]);
            }
        }
    }
}

// ======================= GEMM1: gathered x @ W1[e], +b1, ReLU -> g_hhi/g_hlo =======================
__global__ void __launch_bounds__(256, 2) gemm1_mma(const float* __restrict__ x,
                                                    const float* __restrict__ W1,
                                                    const float* __restrict__ b1) {
    extern __shared__ char smem[];
    int tid = threadIdx.x, wid = tid >> 5, lane = tid & 31;
    int warp_m = wid & 3, warp_n = wid >> 2;

    int e = blockIdx.z;
    int count = g_counts[e];
    int m0 = blockIdx.y * 128;
    if (m0 >= count) return;
    int n0 = blockIdx.x * 64;

    const float* W1e = W1 + (size_t)e * In * Hn;
    const int* tokp = g_tok + e * Bn;

    float acc[2][4][4];
#pragma unroll
    for (int i = 0; i < 2; i++)
#pragma unroll
        for (int j = 0; j < 4; j++)
#pragma unroll
            for (int k = 0; k < 4; k++) acc[i][j][k] = 0.f;

    // fill: A = 128 gathered x rows x 32 k (split), B = W1 chunk (split+transpose)
    auto fill = [&](char* buf, int kt) {
        char* Ahi = buf; char* Alo = buf + PLANE_A;
#pragma unroll
        for (int j = 0; j < 2; j++) {
            int idx = tid + j * 256;            // 0..511: row 0..127, chunk 0..3
            int row = idx >> 2, c = idx & 3;
            int gr = m0 + row;
            int tok = tokp[gr < count ? gr : count - 1];
            const float* srcp = x + (size_t)tok * In + kt + c * 8;
            float4 v0 = *reinterpret_cast<const float4*>(srcp);
            float4 v1 = *reinterpret_cast<const float4*>(srcp + 4);
            float f[8] = {v0.x, v0.y, v0.z, v0.w, v1.x, v1.y, v1.z, v1.w};
            uint32_t hi[4], lo[4];
#pragma unroll
            for (int q = 0; q < 4; q++) {
                __nv_bfloat16 h0, l0, h1, l1;
                split_bf16(f[2 * q], h0, l0);
                split_bf16(f[2 * q + 1], h1, l1);
                hi[q] = pack2(h0, h1);
                lo[q] = pack2(l0, l1);
            }
            uint32_t dst = (uint32_t)row * 64 + (uint32_t)((c ^ SWZ_R(row)) * 16);
            *reinterpret_cast<uint4*>(Ahi + dst) = make_uint4(hi[0], hi[1], hi[2], hi[3]);
            *reinterpret_cast<uint4*>(Alo + dst) = make_uint4(lo[0], lo[1], lo[2], lo[3]);
        }
        stage_B_f32(W1e, Hn, kt, n0, tid, buf + 2 * PLANE_A, buf + 2 * PLANE_A + PLANE_Bp);
    };

    char* buf0 = smem;
    char* buf1 = smem + BUF_B;

    const int NC = In / 32;    // 16
    fill(buf0, 0);
    __syncthreads();
    for (int c = 0; c < NC; c++) {
        char* cur = (c & 1) ? buf1 : buf0;
        char* nxt = (c & 1) ? buf0 : buf1;
        if (c + 1 < NC) fill(nxt, (c + 1) * 32);
        compute_tile(cur, lane, warp_m, warp_n, acc);
        __syncthreads();
    }

    // epilogue: +bias, ReLU, split -> g_hhi/g_hlo
#pragma unroll
    for (int mt = 0; mt < 2; mt++) {
        int row_l = warp_m * 32 + mt * 16 + (lane >> 2);
#pragma unroll
        for (int nt = 0; nt < 4; nt++) {
            int ncol_l = warp_n * 32 + nt * 8 + (lane & 3) * 2;
            float bb0 = b1[e * Hn + n0 + ncol_l];
            float bb1 = b1[e * Hn + n0 + ncol_l + 1];
#pragma unroll
            for (int h = 0; h < 2; h++) {
                int grow = m0 + row_l + h * 8;
                float v0 = fmaxf(acc[mt][nt][h * 2 + 0] + bb0, 0.f);
                float v1 = fmaxf(acc[mt][nt][h * 2 + 1] + bb1, 0.f);
                __nv_bfloat16 h0, h1, l0, l1;
                split_bf16(v0, h0, l0); split_bf16(v1, h1, l1);
                size_t off = (size_t)(e * Bn + grow) * Hn + n0 + ncol_l;
                *reinterpret_cast<uint32_t*>(g_hhi + off) = pack2(h0, h1);
                *reinterpret_cast<uint32_t*>(g_hlo + off) = pack2(l0, l1);
            }
        }
    }
}

// ======================= GEMM2: h(bf16 hi/lo) @ W2[e] -> g_y fp32 =======================
__global__ void __launch_bounds__(256, 2) gemm2_mma(const float* __restrict__ W2) {
    extern __shared__ char smem[];
    int tid = threadIdx.x, wid = tid >> 5, lane = tid & 31;
    int warp_m = wid & 3, warp_n = wid >> 2;

    int e = blockIdx.z;
    int count = g_counts[e];
    int m0 = blockIdx.y * 128;
    if (m0 >= count) return;
    int n0 = blockIdx.x * 64;

    const __nv_bfloat16* Ahg = g_hhi + (size_t)(e * Bn + m0) * Hn;
    const __nv_bfloat16* Alg = g_hlo + (size_t)(e * Bn + m0) * Hn;
    const float* W2e = W2 + (size_t)e * Hn * On;

    float acc[2][4][4];
#pragma unroll
    for (int i = 0; i < 2; i++)
#pragma unroll
        for (int j = 0; j < 4; j++)
#pragma unroll
            for (int k = 0; k < 4; k++) acc[i][j][k] = 0.f;

    // fill: A = pure uint4 copies of bf16 hi/lo, B = W2 chunk
    auto fill = [&](char* buf, int kt) {
        char* Ahi = buf; char* Alo = buf + PLANE_A;
#pragma unroll
        for (int j = 0; j < 2; j++) {
            int idx = tid + j * 256;            // 0..511: row 0..127, chunk 0..3
            int row = idx >> 2, c = idx & 3;
            size_t src = (size_t)row * Hn + kt + c * 8;
            uint32_t dst = (uint32_t)row * 64 + (uint32_t)((c ^ SWZ_R(row)) * 16);
            *reinterpret_cast<uint4*>(Ahi + dst) = *reinterpret_cast<const uint4*>(Ahg + src);
            *reinterpret_cast<uint4*>(Alo + dst) = *reinterpret_cast<const uint4*>(Alg + src);
        }
        stage_B_f32(W2e, On, kt, n0, tid, buf + 2 * PLANE_A, buf + 2 * PLANE_A + PLANE_Bp);
    };

    char* buf0 = smem;
    char* buf1 = smem + BUF_B;

    const int NC = Hn / 32;    // 64
    fill(buf0, 0);
    __syncthreads();
    for (int c = 0; c < NC; c++) {
        char* cur = (c & 1) ? buf1 : buf0;
        char* nxt = (c & 1) ? buf0 : buf1;
        if (c + 1 < NC) fill(nxt, (c + 1) * 32);
        compute_tile(cur, lane, warp_m, warp_n, acc);
        __syncthreads();
    }

#pragma unroll
    for (int mt = 0; mt < 2; mt++) {
        int row_l = warp_m * 32 + mt * 16 + (lane >> 2);
#pragma unroll
        for (int nt = 0; nt < 4; nt++) {
            int ncol_l = warp_n * 32 + nt * 8 + (lane & 3) * 2;
#pragma unroll
            for (int h = 0; h < 2; h++) {
                int grow = m0 + row_l + h * 8;
                float2 v = make_float2(acc[mt][nt][h * 2 + 0], acc[mt][nt][h * 2 + 1]);
                *reinterpret_cast<float2*>(g_y + (size_t)(e * Bn + grow) * On + n0 + ncol_l) = v;
            }
        }
    }
}

// ---------------- combine (+ b2) — proven ----------------
__global__ void combine_kernel(const float* __restrict__ b2, float* __restrict__ out) {
    int idx = blockIdx.x * 256 + threadIdx.x;
    int b = idx >> 7;
    int o = (idx & 127) * 4;
    int p0 = g_pos[b * 2 + 0], p1 = g_pos[b * 2 + 1];
    float w0 = g_wk[b * 2 + 0], w1 = g_wk[b * 2 + 1];
    int e0 = p0 >> 10, e1 = p1 >> 10;
    float4 y0 = *reinterpret_cast<const float4*>(g_y + (size_t)p0 * On + o);
    float4 y1 = *reinterpret_cast<const float4*>(g_y + (size_t)p1 * On + o);
    float4 c0 = *reinterpret_cast<const float4*>(b2 + (size_t)e0 * On + o);
    float4 c1 = *reinterpret_cast<const float4*>(b2 + (size_t)e1 * On + o);
    float4 r;
    r.x = w0 * (y0.x + c0.x) + w1 * (y1.x + c1.x);
    r.y = w0 * (y0.y + c0.y) + w1 * (y1.y + c1.y);
    r.z = w0 * (y0.z + c0.z) + w1 * (y1.z + c1.z);
    r.w = w0 * (y0.w + c0.w) + w1 * (y1.w + c1.w);
    *reinterpret_cast<float4*>(out + (size_t)b * On + o) = r;
}

// ---------------- launch ----------------
extern "C" void kernel_launch(void* const* d_in, const int* in_sizes, int n_in,
                              void* d_out, int out_size) {
    const float* x  = (const float*)d_in[0];
    const float* Wg = (const float*)d_in[1];
    const float* bg = (const float*)d_in[2];
    const float* W1 = (const float*)d_in[3];
    const float* b1 = (const float*)d_in[4];
    const float* W2 = (const float*)d_in[5];
    const float* b2 = (const float*)d_in[6];
    float* out = (float*)d_out;

    zero_counts_kernel<<<1, 32>>>();
    gate_kernel<<<Bn / 8, 256>>>(x, Wg, bg);
    gemm1_mma<<<dim3(Hn / 64, Bn / 128, En), 256, GSMEM>>>(x, W1, b1);
    gemm2_mma<<<dim3(On / 64, Bn / 128, En), 256, GSMEM>>>(W2);
    combine_kernel<<<(Bn * On / 4) / 256, 256>>>(b2, out);
}

// round 10
// speedup vs baseline: 2.5997x; 1.1276x over previous
#include <cuda_runtime.h>
#include <cuda_bf16.h>
#include <math.h>
#include <stdint.h>

#define Bn 1024
#define In 512
#define Hn 2048
#define On 512
#define En 8

// ---------------- scratch (device globals; zero-init, 16B aligned; ~80MB proven budget) ----------------
__device__ __align__(16) int   g_counts[En];
__device__ __align__(16) int   g_tok[En * Bn];
__device__ __align__(16) int   g_pos[Bn * 2];
__device__ __align__(16) float g_wk[Bn * 2];
__device__ __align__(16) __nv_bfloat16 g_hhi[En * Bn * Hn];   // 32 MB
__device__ __align__(16) __nv_bfloat16 g_hlo[En * Bn * Hn];   // 32 MB
__device__ __align__(16) float g_y[En * Bn * On];             // 16 MB

// ---------------- mma / ldmatrix helpers ----------------
__device__ __forceinline__ void mma_bf16(float* c, const uint32_t* a, const uint32_t* b) {
    asm volatile(
        "mma.sync.aligned.m16n8k16.row.col.f32.bf16.bf16.f32 "
        "{%0,%1,%2,%3}, {%4,%5,%6,%7}, {%8,%9}, {%0,%1,%2,%3};"
        : "+f"(c[0]), "+f"(c[1]), "+f"(c[2]), "+f"(c[3])
        : "r"(a[0]), "r"(a[1]), "r"(a[2]), "r"(a[3]), "r"(b[0]), "r"(b[1]));
}
__device__ __forceinline__ void ldsm_x4(uint32_t& r0, uint32_t& r1, uint32_t& r2, uint32_t& r3,
                                        uint32_t addr) {
    asm volatile("ldmatrix.sync.aligned.m8n8.x4.shared.b16 {%0,%1,%2,%3}, [%4];"
        : "=r"(r0), "=r"(r1), "=r"(r2), "=r"(r3) : "r"(addr));
}

__device__ __forceinline__ void split_bf16(float v, __nv_bfloat16& h, __nv_bfloat16& l) {
    h = __float2bfloat16(v);
    l = __float2bfloat16(v - __bfloat162float(h));
}
__device__ __forceinline__ uint32_t pack2(__nv_bfloat16 a, __nv_bfloat16 b) {
    return ((uint32_t)__bfloat16_as_ushort(b) << 16) | __bfloat16_as_ushort(a);
}

// ---------------- pad-free swizzled smem plane (proven R9) ----------------
// plane: rows x 32 k bf16 = 64 B/row = 4 chunks of 16 B.
// phys(r, chunk c) = r*64 + ((c ^ ((r>>1)&3)) * 16)
#define PLANE_Bp 4096                 // 64 rows
#define SWZ_R(r) (((r) >> 1) & 3)

#define PLANE_A1 8192                 // gemm1 A: 128 rows
#define BUF1_B   (2 * PLANE_A1 + 2 * PLANE_Bp)   // 24576
#define GSMEM1   (2 * BUF1_B)                    // 49152 (= default 48KB max, proven R9)

#define PLANE_A2 4096                 // gemm2 A: 64 rows
#define BUF2_B   (2 * PLANE_A2 + 2 * PLANE_Bp)   // 16384
#define GSMEM2   (2 * BUF2_B)                    // 32768

// ---------------- kernel 0: zero counters ----------------
__global__ void zero_counts_kernel() {
    if (threadIdx.x < En) g_counts[threadIdx.x] = 0;
}

// ---------------- kernel 1: gating (proven) ----------------
__global__ void gate_kernel(const float* __restrict__ x,
                            const float* __restrict__ Wg,
                            const float* __restrict__ bg) {
    int warp = threadIdx.x >> 5, lane = threadIdx.x & 31;
    int b = blockIdx.x * 8 + warp;
    const float* xr = x + (size_t)b * In;

    float acc[En];
#pragma unroll
    for (int e = 0; e < En; e++) acc[e] = 0.f;
    for (int i = lane; i < In; i += 32) {
        float xv = xr[i];
        const float4* w4 = reinterpret_cast<const float4*>(Wg + (size_t)i * En);
        float4 w0 = w4[0], w1 = w4[1];
        acc[0] += xv * w0.x; acc[1] += xv * w0.y;
        acc[2] += xv * w0.z; acc[3] += xv * w0.w;
        acc[4] += xv * w1.x; acc[5] += xv * w1.y;
        acc[6] += xv * w1.z; acc[7] += xv * w1.w;
    }
#pragma unroll
    for (int e = 0; e < En; e++) {
#pragma unroll
        for (int off = 16; off; off >>= 1)
            acc[e] += __shfl_xor_sync(0xffffffffu, acc[e], off);
    }
    if (lane == 0) {
        float lg[En]; float m = -1e30f;
#pragma unroll
        for (int e = 0; e < En; e++) { lg[e] = acc[e] + bg[e]; m = fmaxf(m, lg[e]); }
        float p[En]; float s = 0.f;
#pragma unroll
        for (int e = 0; e < En; e++) { p[e] = expf(lg[e] - m); s += p[e]; }
#pragma unroll
        for (int e = 0; e < En; e++) p[e] /= s;
        int i0 = 0;
#pragma unroll
        for (int e = 1; e < En; e++) if (p[e] > p[i0]) i0 = e;
        int i1 = (i0 == 0) ? 1 : 0;
#pragma unroll
        for (int e = 0; e < En; e++) if (e != i0 && p[e] > p[i1]) i1 = e;
        float sum2 = p[i0] + p[i1];
        float w0 = p[i0] / sum2, w1 = p[i1] / sum2;
        int s0 = atomicAdd(&g_counts[i0], 1);
        g_tok[i0 * Bn + s0] = b;
        g_pos[b * 2 + 0] = i0 * Bn + s0;
        g_wk[b * 2 + 0] = w0;
        int s1 = atomicAdd(&g_counts[i1], 1);
        g_tok[i1 * Bn + s1] = b;
        g_pos[b * 2 + 1] = i1 * Bn + s1;
        g_wk[b * 2 + 1] = w1;
    }
}

// ---------------- B staging: fp32 W[k][n] -> smem [n][k] bf16 hi/lo (swizzled; proven R9) ----------------
__device__ __forceinline__ void stage_B_f32(const float* __restrict__ W, size_t Nld,
                                            int kt, int n0, int tid,
                                            char* Bhi, char* Blo) {
    int n = tid & 63, kg = tid >> 6;
    const float* src = W + (size_t)(kt + kg * 8) * Nld + n0 + n;
    float f[8];
#pragma unroll
    for (int j = 0; j < 8; j++) f[j] = src[(size_t)j * Nld];
    uint32_t hi[4], lo[4];
#pragma unroll
    for (int j = 0; j < 4; j++) {
        __nv_bfloat16 h0, l0, h1, l1;
        split_bf16(f[2 * j], h0, l0);
        split_bf16(f[2 * j + 1], h1, l1);
        hi[j] = pack2(h0, h1);
        lo[j] = pack2(l0, l1);
    }
    uint32_t dst = (uint32_t)n * 64 + (uint32_t)((kg ^ SWZ_R(n)) * 16);
    *reinterpret_cast<uint4*>(Bhi + dst) = make_uint4(hi[0], hi[1], hi[2], hi[3]);
    *reinterpret_cast<uint4*>(Blo + dst) = make_uint4(lo[0], lo[1], lo[2], lo[3]);
}

// ---------------- compute via ldmatrix.x4: MT m-subtiles (16 rows each) x 4 nt x 3 MMAs ----------------
template <int MT, int AP>
__device__ __forceinline__ void compute_tile(uint32_t sbuf, int lane, int warp_m, int warp_n,
                                             float acc[MT][4][4]) {
    uint32_t Ahi = sbuf, Alo = sbuf + AP;
    uint32_t Bhi = sbuf + 2 * AP, Blo = Bhi + PLANE_Bp;
    int rsel = lane & 7, grp = lane >> 3;
#pragma unroll
    for (int ks = 0; ks < 2; ks++) {
        uint32_t bh[4][2], bl[4][2];
#pragma unroll
        for (int p = 0; p < 2; p++) {
            // matrices: {nt=2p, kblk 2ks}, {nt=2p, 2ks+1}, {nt=2p+1, 2ks}, {nt=2p+1, 2ks+1}
            int nt = 2 * p + (grp >> 1);
            int n = warp_n * 32 + nt * 8 + rsel;
            int cB = 2 * ks + (grp & 1);
            uint32_t off = (uint32_t)n * 64 + (uint32_t)((cB ^ SWZ_R(n)) << 4);
            ldsm_x4(bh[2 * p][0], bh[2 * p][1], bh[2 * p + 1][0], bh[2 * p + 1][1], Bhi + off);
            ldsm_x4(bl[2 * p][0], bl[2 * p][1], bl[2 * p + 1][0], bl[2 * p + 1][1], Blo + off);
        }
#pragma unroll
        for (int mt = 0; mt < MT; mt++) {
            // matrices: {rows 0-7, kblk 2ks}, {rows 8-15, 2ks}, {rows 0-7, 2ks+1}, {rows 8-15, 2ks+1}
            int r = warp_m * (MT * 16) + mt * 16 + ((grp & 1) << 3) + rsel;
            int cA = 2 * ks + (grp >> 1);
            uint32_t off = (uint32_t)r * 64 + (uint32_t)((cA ^ SWZ_R(r)) << 4);
            uint32_t ah[4], al[4];
            ldsm_x4(ah[0], ah[1], ah[2], ah[3], Ahi + off);
            ldsm_x4(al[0], al[1], al[2], al[3], Alo + off);
#pragma unroll
            for (int nt = 0; nt < 4; nt++) {
                mma_bf16(acc[mt][nt], ah, bh[nt]);
                mma_bf16(acc[mt][nt], ah, bl[nt]);
                mma_bf16(acc[mt][nt], al, bh[nt]);
            }
        }
    }
}

// ======================= GEMM1: gathered x @ W1[e], +b1, ReLU -> g_hhi/g_hlo =======================
// M=128, N=64. warp_m = wid&3 (32 rows), warp_n = wid>>2 (32 cols).
__global__ void __launch_bounds__(256, 2) gemm1_mma(const float* __restrict__ x,
                                                    const float* __restrict__ W1,
                                                    const float* __restrict__ b1) {
    extern __shared__ char smem[];
    uint32_t sbase = (uint32_t)__cvta_generic_to_shared(smem);
    int tid = threadIdx.x, wid = tid >> 5, lane = tid & 31;
    int warp_m = wid & 3, warp_n = wid >> 2;

    int e = blockIdx.z;
    int count = g_counts[e];
    int m0 = blockIdx.y * 128;
    if (m0 >= count) return;
    int n0 = blockIdx.x * 64;

    const float* W1e = W1 + (size_t)e * In * Hn;
    const int* tokp = g_tok + e * Bn;

    float acc[2][4][4];
#pragma unroll
    for (int i = 0; i < 2; i++)
#pragma unroll
        for (int j = 0; j < 4; j++)
#pragma unroll
            for (int k = 0; k < 4; k++) acc[i][j][k] = 0.f;

    auto fill = [&](char* buf, int kt) {
        char* Ahi = buf; char* Alo = buf + PLANE_A1;
#pragma unroll
        for (int j = 0; j < 2; j++) {
            int idx = tid + j * 256;            // 0..511: row 0..127, chunk 0..3
            int row = idx >> 2, c = idx & 3;
            int gr = m0 + row;
            int tok = tokp[gr < count ? gr : count - 1];
            const float* srcp = x + (size_t)tok * In + kt + c * 8;
            float4 v0 = *reinterpret_cast<const float4*>(srcp);
            float4 v1 = *reinterpret_cast<const float4*>(srcp + 4);
            float f[8] = {v0.x, v0.y, v0.z, v0.w, v1.x, v1.y, v1.z, v1.w};
            uint32_t hi[4], lo[4];
#pragma unroll
            for (int q = 0; q < 4; q++) {
                __nv_bfloat16 h0, l0, h1, l1;
                split_bf16(f[2 * q], h0, l0);
                split_bf16(f[2 * q + 1], h1, l1);
                hi[q] = pack2(h0, h1);
                lo[q] = pack2(l0, l1);
            }
            uint32_t dst = (uint32_t)row * 64 + (uint32_t)((c ^ SWZ_R(row)) * 16);
            *reinterpret_cast<uint4*>(Ahi + dst) = make_uint4(hi[0], hi[1], hi[2], hi[3]);
            *reinterpret_cast<uint4*>(Alo + dst) = make_uint4(lo[0], lo[1], lo[2], lo[3]);
        }
        stage_B_f32(W1e, Hn, kt, n0, tid, buf + 2 * PLANE_A1, buf + 2 * PLANE_A1 + PLANE_Bp);
    };

    const int NC = In / 32;    // 16
    fill(smem, 0);
    __syncthreads();
    for (int c = 0; c < NC; c++) {
        uint32_t curo = (c & 1) ? BUF1_B : 0;
        char* nxt = smem + ((c & 1) ? 0 : BUF1_B);
        if (c + 1 < NC) fill(nxt, (c + 1) * 32);
        compute_tile<2, PLANE_A1>(sbase + curo, lane, warp_m, warp_n, acc);
        __syncthreads();
    }

    // epilogue: +bias, ReLU, split -> g_hhi/g_hlo
#pragma unroll
    for (int mt = 0; mt < 2; mt++) {
        int row_l = warp_m * 32 + mt * 16 + (lane >> 2);
#pragma unroll
        for (int nt = 0; nt < 4; nt++) {
            int ncol_l = warp_n * 32 + nt * 8 + (lane & 3) * 2;
            float bb0 = b1[e * Hn + n0 + ncol_l];
            float bb1 = b1[e * Hn + n0 + ncol_l + 1];
#pragma unroll
            for (int h = 0; h < 2; h++) {
                int grow = m0 + row_l + h * 8;
                float v0 = fmaxf(acc[mt][nt][h * 2 + 0] + bb0, 0.f);
                float v1 = fmaxf(acc[mt][nt][h * 2 + 1] + bb1, 0.f);
                __nv_bfloat16 h0, h1, l0, l1;
                split_bf16(v0, h0, l0); split_bf16(v1, h1, l1);
                size_t off = (size_t)(e * Bn + grow) * Hn + n0 + ncol_l;
                *reinterpret_cast<uint32_t*>(g_hhi + off) = pack2(h0, h1);
                *reinterpret_cast<uint32_t*>(g_hlo + off) = pack2(l0, l1);
            }
        }
    }
}

// ======================= GEMM2: h(bf16 hi/lo) @ W2[e] -> g_y fp32 =======================
// M=64, N=64. warp_m = wid&3 (16 rows), warp_n = wid>>2 (32 cols). 256 active blocks.
__global__ void __launch_bounds__(256, 2) gemm2_mma(const float* __restrict__ W2) {
    extern __shared__ char smem[];
    uint32_t sbase = (uint32_t)__cvta_generic_to_shared(smem);
    int tid = threadIdx.x, wid = tid >> 5, lane = tid & 31;
    int warp_m = wid & 3, warp_n = wid >> 2;

    int e = blockIdx.z;
    int count = g_counts[e];
    int m0 = blockIdx.y * 64;
    if (m0 >= count) return;
    int n0 = blockIdx.x * 64;

    const __nv_bfloat16* Ahg = g_hhi + (size_t)(e * Bn + m0) * Hn;
    const __nv_bfloat16* Alg = g_hlo + (size_t)(e * Bn + m0) * Hn;
    const float* W2e = W2 + (size_t)e * Hn * On;

    float acc[1][4][4];
#pragma unroll
    for (int j = 0; j < 4; j++)
#pragma unroll
        for (int k = 0; k < 4; k++) acc[0][j][k] = 0.f;

    auto fill = [&](char* buf, int kt) {
        char* Ahi = buf; char* Alo = buf + PLANE_A2;
        int row = tid >> 2, c = tid & 3;      // 64 rows x 4 chunks = 256
        size_t src = (size_t)row * Hn + kt + c * 8;
        uint32_t dst = (uint32_t)row * 64 + (uint32_t)((c ^ SWZ_R(row)) * 16);
        *reinterpret_cast<uint4*>(Ahi + dst) = *reinterpret_cast<const uint4*>(Ahg + src);
        *reinterpret_cast<uint4*>(Alo + dst) = *reinterpret_cast<const uint4*>(Alg + src);
        stage_B_f32(W2e, On, kt, n0, tid, buf + 2 * PLANE_A2, buf + 2 * PLANE_A2 + PLANE_Bp);
    };

    const int NC = Hn / 32;    // 64
    fill(smem, 0);
    __syncthreads();
    for (int c = 0; c < NC; c++) {
        uint32_t curo = (c & 1) ? BUF2_B : 0;
        char* nxt = smem + ((c & 1) ? 0 : BUF2_B);
        if (c + 1 < NC) fill(nxt, (c + 1) * 32);
        compute_tile<1, PLANE_A2>(sbase + curo, lane, warp_m, warp_n, acc);
        __syncthreads();
    }

#pragma unroll
    for (int nt = 0; nt < 4; nt++) {
        int ncol_l = warp_n * 32 + nt * 8 + (lane & 3) * 2;
#pragma unroll
        for (int h = 0; h < 2; h++) {
            int grow = m0 + warp_m * 16 + (lane >> 2) + h * 8;
            float2 v = make_float2(acc[0][nt][h * 2 + 0], acc[0][nt][h * 2 + 1]);
            *reinterpret_cast<float2*>(g_y + (size_t)(e * Bn + grow) * On + n0 + ncol_l) = v;
        }
    }
}

// ---------------- combine (+ b2) — proven ----------------
__global__ void combine_kernel(const float* __restrict__ b2, float* __restrict__ out) {
    int idx = blockIdx.x * 256 + threadIdx.x;
    int b = idx >> 7;
    int o = (idx & 127) * 4;
    int p0 = g_pos[b * 2 + 0], p1 = g_pos[b * 2 + 1];
    float w0 = g_wk[b * 2 + 0], w1 = g_wk[b * 2 + 1];
    int e0 = p0 >> 10, e1 = p1 >> 10;
    float4 y0 = *reinterpret_cast<const float4*>(g_y + (size_t)p0 * On + o);
    float4 y1 = *reinterpret_cast<const float4*>(g_y + (size_t)p1 * On + o);
    float4 c0 = *reinterpret_cast<const float4*>(b2 + (size_t)e0 * On + o);
    float4 c1 = *reinterpret_cast<const float4*>(b2 + (size_t)e1 * On + o);
    float4 r;
    r.x = w0 * (y0.x + c0.x) + w1 * (y1.x + c1.x);
    r.y = w0 * (y0.y + c0.y) + w1 * (y1.y + c1.y);
    r.z = w0 * (y0.z + c0.z) + w1 * (y1.z + c1.z);
    r.w = w0 * (y0.w + c0.w) + w1 * (y1.w + c1.w);
    *reinterpret_cast<float4*>(out + (size_t)b * On + o) = r;
}

// ---------------- launch ----------------
extern "C" void kernel_launch(void* const* d_in, const int* in_sizes, int n_in,
                              void* d_out, int out_size) {
    const float* x  = (const float*)d_in[0];
    const float* Wg = (const float*)d_in[1];
    const float* bg = (const float*)d_in[2];
    const float* W1 = (const float*)d_in[3];
    const float* b1 = (const float*)d_in[4];
    const float* W2 = (const float*)d_in[5];
    const float* b2 = (const float*)d_in[6];
    float* out = (float*)d_out;

    zero_counts_kernel<<<1, 32>>>();
    gate_kernel<<<Bn / 8, 256>>>(x, Wg, bg);
    gemm1_mma<<<dim3(Hn / 64, Bn / 128, En), 256, GSMEM1>>>(x, W1, b1);
    gemm2_mma<<<dim3(On / 64, Bn / 64, En), 256, GSMEM2>>>(W2);
    combine_kernel<<<(Bn * On / 4) / 256, 256>>>(b2, out);
}

// round 11
// speedup vs baseline: 3.0704x; 1.1810x over previous
#include <cuda_runtime.h>
#include <cuda_bf16.h>
#include <math.h>
#include <stdint.h>

#define Bn 1024
#define In 512
#define Hn 2048
#define On 512
#define En 8

// ---------------- scratch (device globals; zero-init, 16B aligned; ~80MB proven budget) ----------------
__device__ __align__(16) int   g_counts[En];
__device__ __align__(16) int   g_tok[En * Bn];
__device__ __align__(16) int   g_pos[Bn * 2];
__device__ __align__(16) float g_wk[Bn * 2];
__device__ __align__(16) __nv_bfloat16 g_hhi[En * Bn * Hn];   // 32 MB
__device__ __align__(16) __nv_bfloat16 g_hlo[En * Bn * Hn];   // 32 MB
__device__ __align__(16) float g_y[En * Bn * On];             // 16 MB

// ---------------- mma / ldmatrix / cp.async helpers ----------------
__device__ __forceinline__ void mma_bf16(float* c, const uint32_t* a, const uint32_t* b) {
    asm volatile(
        "mma.sync.aligned.m16n8k16.row.col.f32.bf16.bf16.f32 "
        "{%0,%1,%2,%3}, {%4,%5,%6,%7}, {%8,%9}, {%0,%1,%2,%3};"
        : "+f"(c[0]), "+f"(c[1]), "+f"(c[2]), "+f"(c[3])
        : "r"(a[0]), "r"(a[1]), "r"(a[2]), "r"(a[3]), "r"(b[0]), "r"(b[1]));
}
__device__ __forceinline__ void ldsm_x4(uint32_t& r0, uint32_t& r1, uint32_t& r2, uint32_t& r3,
                                        uint32_t addr) {
    asm volatile("ldmatrix.sync.aligned.m8n8.x4.shared.b16 {%0,%1,%2,%3}, [%4];"
        : "=r"(r0), "=r"(r1), "=r"(r2), "=r"(r3) : "r"(addr));
}
#define CP16(dst, src) asm volatile("cp.async.cg.shared.global [%0], [%1], 16;" :: "r"(dst), "l"(src))
#define CPCOMMIT()     asm volatile("cp.async.commit_group;" ::: "memory")
#define CPWAIT1()      asm volatile("cp.async.wait_group 1;" ::: "memory")
#define CPWAIT0()      asm volatile("cp.async.wait_group 0;" ::: "memory")

__device__ __forceinline__ void split_bf16(float v, __nv_bfloat16& h, __nv_bfloat16& l) {
    h = __float2bfloat16(v);
    l = __float2bfloat16(v - __bfloat162float(h));
}
__device__ __forceinline__ uint32_t pack2(__nv_bfloat16 a, __nv_bfloat16 b) {
    return ((uint32_t)__bfloat16_as_ushort(b) << 16) | __bfloat16_as_ushort(a);
}

// ---------------- pad-free swizzled smem plane (proven R9/R10) ----------------
// plane: rows x 32 k bf16 = 64 B/row = 4 chunks of 16 B.
// phys(r, chunk c) = r*64 + ((c ^ ((r>>1)&3)) * 16)
#define PLANE_Bp 4096                 // 64 rows
#define SWZ_R(r) (((r) >> 1) & 3)

#define PLANE_A1 8192                 // gemm1 A: 128 rows
#define BUF1_B   (2 * PLANE_A1 + 2 * PLANE_Bp)   // 24576
#define GSMEM1   (2 * BUF1_B)                    // 49152 (proven)

#define PLANE_A2 4096                 // gemm2 A: 64 rows
#define BUF2_B   (2 * PLANE_A2 + 2 * PLANE_Bp)   // 16384
#define GSMEM2   (3 * BUF2_B)                    // 49152: TRIPLE buffer (= default max, proven size)

// ---------------- kernel 0: zero counters ----------------
__global__ void zero_counts_kernel() {
    if (threadIdx.x < En) g_counts[threadIdx.x] = 0;
}

// ---------------- kernel 1: gating (proven) ----------------
__global__ void gate_kernel(const float* __restrict__ x,
                            const float* __restrict__ Wg,
                            const float* __restrict__ bg) {
    int warp = threadIdx.x >> 5, lane = threadIdx.x & 31;
    int b = blockIdx.x * 8 + warp;
    const float* xr = x + (size_t)b * In;

    float acc[En];
#pragma unroll
    for (int e = 0; e < En; e++) acc[e] = 0.f;
    for (int i = lane; i < In; i += 32) {
        float xv = xr[i];
        const float4* w4 = reinterpret_cast<const float4*>(Wg + (size_t)i * En);
        float4 w0 = w4[0], w1 = w4[1];
        acc[0] += xv * w0.x; acc[1] += xv * w0.y;
        acc[2] += xv * w0.z; acc[3] += xv * w0.w;
        acc[4] += xv * w1.x; acc[5] += xv * w1.y;
        acc[6] += xv * w1.z; acc[7] += xv * w1.w;
    }
#pragma unroll
    for (int e = 0; e < En; e++) {
#pragma unroll
        for (int off = 16; off; off >>= 1)
            acc[e] += __shfl_xor_sync(0xffffffffu, acc[e], off);
    }
    if (lane == 0) {
        float lg[En]; float m = -1e30f;
#pragma unroll
        for (int e = 0; e < En; e++) { lg[e] = acc[e] + bg[e]; m = fmaxf(m, lg[e]); }
        float p[En]; float s = 0.f;
#pragma unroll
        for (int e = 0; e < En; e++) { p[e] = expf(lg[e] - m); s += p[e]; }
#pragma unroll
        for (int e = 0; e < En; e++) p[e] /= s;
        int i0 = 0;
#pragma unroll
        for (int e = 1; e < En; e++) if (p[e] > p[i0]) i0 = e;
        int i1 = (i0 == 0) ? 1 : 0;
#pragma unroll
        for (int e = 0; e < En; e++) if (e != i0 && p[e] > p[i1]) i1 = e;
        float sum2 = p[i0] + p[i1];
        float w0 = p[i0] / sum2, w1 = p[i1] / sum2;
        int s0 = atomicAdd(&g_counts[i0], 1);
        g_tok[i0 * Bn + s0] = b;
        g_pos[b * 2 + 0] = i0 * Bn + s0;
        g_wk[b * 2 + 0] = w0;
        int s1 = atomicAdd(&g_counts[i1], 1);
        g_tok[i1 * Bn + s1] = b;
        g_pos[b * 2 + 1] = i1 * Bn + s1;
        g_wk[b * 2 + 1] = w1;
    }
}

// ---------------- B staging (proven R9/R10): fp32 W[k][n] -> smem [n][k] bf16 hi/lo ----------------
__device__ __forceinline__ void stage_B_f32(const float* __restrict__ W, size_t Nld,
                                            int kt, int n0, int tid,
                                            char* Bhi, char* Blo) {
    int n = tid & 63, kg = tid >> 6;
    const float* src = W + (size_t)(kt + kg * 8) * Nld + n0 + n;
    float f[8];
#pragma unroll
    for (int j = 0; j < 8; j++) f[j] = src[(size_t)j * Nld];
    uint32_t hi[4], lo[4];
#pragma unroll
    for (int j = 0; j < 4; j++) {
        __nv_bfloat16 h0, l0, h1, l1;
        split_bf16(f[2 * j], h0, l0);
        split_bf16(f[2 * j + 1], h1, l1);
        hi[j] = pack2(h0, h1);
        lo[j] = pack2(l0, l1);
    }
    uint32_t dst = (uint32_t)n * 64 + (uint32_t)((kg ^ SWZ_R(n)) * 16);
    *reinterpret_cast<uint4*>(Bhi + dst) = make_uint4(hi[0], hi[1], hi[2], hi[3]);
    *reinterpret_cast<uint4*>(Blo + dst) = make_uint4(lo[0], lo[1], lo[2], lo[3]);
}

// ---------------- compute via ldmatrix.x4 (proven R10) ----------------
template <int MT, int AP>
__device__ __forceinline__ void compute_tile(uint32_t sbuf, int lane, int warp_m, int warp_n,
                                             float acc[MT][4][4]) {
    uint32_t Ahi = sbuf, Alo = sbuf + AP;
    uint32_t Bhi = sbuf + 2 * AP, Blo = Bhi + PLANE_Bp;
    int rsel = lane & 7, grp = lane >> 3;
#pragma unroll
    for (int ks = 0; ks < 2; ks++) {
        uint32_t bh[4][2], bl[4][2];
#pragma unroll
        for (int p = 0; p < 2; p++) {
            int nt = 2 * p + (grp >> 1);
            int n = warp_n * 32 + nt * 8 + rsel;
            int cB = 2 * ks + (grp & 1);
            uint32_t off = (uint32_t)n * 64 + (uint32_t)((cB ^ SWZ_R(n)) << 4);
            ldsm_x4(bh[2 * p][0], bh[2 * p][1], bh[2 * p + 1][0], bh[2 * p + 1][1], Bhi + off);
            ldsm_x4(bl[2 * p][0], bl[2 * p][1], bl[2 * p + 1][0], bl[2 * p + 1][1], Blo + off);
        }
#pragma unroll
        for (int mt = 0; mt < MT; mt++) {
            int r = warp_m * (MT * 16) + mt * 16 + ((grp & 1) << 3) + rsel;
            int cA = 2 * ks + (grp >> 1);
            uint32_t off = (uint32_t)r * 64 + (uint32_t)((cA ^ SWZ_R(r)) << 4);
            uint32_t ah[4], al[4];
            ldsm_x4(ah[0], ah[1], ah[2], ah[3], Ahi + off);
            ldsm_x4(al[0], al[1], al[2], al[3], Alo + off);
#pragma unroll
            for (int nt = 0; nt < 4; nt++) {
                mma_bf16(acc[mt][nt], ah, bh[nt]);
                mma_bf16(acc[mt][nt], ah, bl[nt]);
                mma_bf16(acc[mt][nt], al, bh[nt]);
            }
        }
    }
}

// ======================= GEMM1 (byte-identical to R10, proven) =======================
__global__ void __launch_bounds__(256, 2) gemm1_mma(const float* __restrict__ x,
                                                    const float* __restrict__ W1,
                                                    const float* __restrict__ b1) {
    extern __shared__ char smem[];
    uint32_t sbase = (uint32_t)__cvta_generic_to_shared(smem);
    int tid = threadIdx.x, wid = tid >> 5, lane = tid & 31;
    int warp_m = wid & 3, warp_n = wid >> 2;

    int e = blockIdx.z;
    int count = g_counts[e];
    int m0 = blockIdx.y * 128;
    if (m0 >= count) return;
    int n0 = blockIdx.x * 64;

    const float* W1e = W1 + (size_t)e * In * Hn;
    const int* tokp = g_tok + e * Bn;

    float acc[2][4][4];
#pragma unroll
    for (int i = 0; i < 2; i++)
#pragma unroll
        for (int j = 0; j < 4; j++)
#pragma unroll
            for (int k = 0; k < 4; k++) acc[i][j][k] = 0.f;

    auto fill = [&](char* buf, int kt) {
        char* Ahi = buf; char* Alo = buf + PLANE_A1;
#pragma unroll
        for (int j = 0; j < 2; j++) {
            int idx = tid + j * 256;
            int row = idx >> 2, c = idx & 3;
            int gr = m0 + row;
            int tok = tokp[gr < count ? gr : count - 1];
            const float* srcp = x + (size_t)tok * In + kt + c * 8;
            float4 v0 = *reinterpret_cast<const float4*>(srcp);
            float4 v1 = *reinterpret_cast<const float4*>(srcp + 4);
            float f[8] = {v0.x, v0.y, v0.z, v0.w, v1.x, v1.y, v1.z, v1.w};
            uint32_t hi[4], lo[4];
#pragma unroll
            for (int q = 0; q < 4; q++) {
                __nv_bfloat16 h0, l0, h1, l1;
                split_bf16(f[2 * q], h0, l0);
                split_bf16(f[2 * q + 1], h1, l1);
                hi[q] = pack2(h0, h1);
                lo[q] = pack2(l0, l1);
            }
            uint32_t dst = (uint32_t)row * 64 + (uint32_t)((c ^ SWZ_R(row)) * 16);
            *reinterpret_cast<uint4*>(Ahi + dst) = make_uint4(hi[0], hi[1], hi[2], hi[3]);
            *reinterpret_cast<uint4*>(Alo + dst) = make_uint4(lo[0], lo[1], lo[2], lo[3]);
        }
        stage_B_f32(W1e, Hn, kt, n0, tid, buf + 2 * PLANE_A1, buf + 2 * PLANE_A1 + PLANE_Bp);
    };

    const int NC = In / 32;    // 16
    fill(smem, 0);
    __syncthreads();
    for (int c = 0; c < NC; c++) {
        uint32_t curo = (c & 1) ? BUF1_B : 0;
        char* nxt = smem + ((c & 1) ? 0 : BUF1_B);
        if (c + 1 < NC) fill(nxt, (c + 1) * 32);
        compute_tile<2, PLANE_A1>(sbase + curo, lane, warp_m, warp_n, acc);
        __syncthreads();
    }

#pragma unroll
    for (int mt = 0; mt < 2; mt++) {
        int row_l = warp_m * 32 + mt * 16 + (lane >> 2);
#pragma unroll
        for (int nt = 0; nt < 4; nt++) {
            int ncol_l = warp_n * 32 + nt * 8 + (lane & 3) * 2;
            float bb0 = b1[e * Hn + n0 + ncol_l];
            float bb1 = b1[e * Hn + n0 + ncol_l + 1];
#pragma unroll
            for (int h = 0; h < 2; h++) {
                int grow = m0 + row_l + h * 8;
                float v0 = fmaxf(acc[mt][nt][h * 2 + 0] + bb0, 0.f);
                float v1 = fmaxf(acc[mt][nt][h * 2 + 1] + bb1, 0.f);
                __nv_bfloat16 h0, h1, l0, l1;
                split_bf16(v0, h0, l0); split_bf16(v1, h1, l1);
                size_t off = (size_t)(e * Bn + grow) * Hn + n0 + ncol_l;
                *reinterpret_cast<uint32_t*>(g_hhi + off) = pack2(h0, h1);
                *reinterpret_cast<uint32_t*>(g_hlo + off) = pack2(l0, l1);
            }
        }
    }
}

// ======================= GEMM2: 3-stage pipeline, cp.async A, split-load B =======================
// M=64, N=64. warp_m = wid&3 (16 rows), warp_n = wid>>2 (32 cols). 256 active blocks.
__global__ void __launch_bounds__(256, 2) gemm2_mma(const float* __restrict__ W2) {
    extern __shared__ char smem[];
    uint32_t sbase = (uint32_t)__cvta_generic_to_shared(smem);
    int tid = threadIdx.x, wid = tid >> 5, lane = tid & 31;
    int warp_m = wid & 3, warp_n = wid >> 2;

    int e = blockIdx.z;
    int count = g_counts[e];
    int m0 = blockIdx.y * 64;
    if (m0 >= count) return;
    int n0 = blockIdx.x * 64;

    const __nv_bfloat16* Ahg = g_hhi + (size_t)(e * Bn + m0) * Hn;
    const __nv_bfloat16* Alg = g_hlo + (size_t)(e * Bn + m0) * Hn;
    const float* W2e = W2 + (size_t)e * Hn * On;

    float acc[1][4][4];
#pragma unroll
    for (int j = 0; j < 4; j++)
#pragma unroll
        for (int k = 0; k < 4; k++) acc[0][j][k] = 0.f;

    int arow = tid >> 2, ach = tid & 3;          // A: 64 rows x 4 chunks
    uint32_t adst = (uint32_t)arow * 64 + (uint32_t)((ach ^ SWZ_R(arow)) * 16);
    int bn = tid & 63, bkg = tid >> 6;           // B: 64 n x 4 k-groups
    uint32_t bdst = (uint32_t)bn * 64 + (uint32_t)((bkg ^ SWZ_R(bn)) * 16);

    float fB[8];                                  // B k-group held across compute

    // A planes: pure 16B cp.async copies (no conversion)
    auto aload = [&](int b, int kt) {
        size_t src = (size_t)arow * Hn + kt + ach * 8;
        uint32_t d = sbase + (uint32_t)(b * BUF2_B) + adst;
        CP16(d, Ahg + src);
        CP16(d + PLANE_A2, Alg + src);
    };
    // B: issue strided LDGs into regs (latency hidden by compute)
    auto bload = [&](int kt) {
        const float* src = W2e + (size_t)(kt + bkg * 8) * On + n0 + bn;
#pragma unroll
        for (int j = 0; j < 8; j++) fB[j] = src[(size_t)j * On];
    };
    // B: convert + STS (after compute)
    auto bstore = [&](int b) {
        uint32_t hi[4], lo[4];
#pragma unroll
        for (int j = 0; j < 4; j++) {
            __nv_bfloat16 h0, l0, h1, l1;
            split_bf16(fB[2 * j], h0, l0);
            split_bf16(fB[2 * j + 1], h1, l1);
            hi[j] = pack2(h0, h1);
            lo[j] = pack2(l0, l1);
        }
        char* base = smem + b * BUF2_B + 2 * PLANE_A2;
        *reinterpret_cast<uint4*>(base + bdst)            = make_uint4(hi[0], hi[1], hi[2], hi[3]);
        *reinterpret_cast<uint4*>(base + PLANE_Bp + bdst) = make_uint4(lo[0], lo[1], lo[2], lo[3]);
    };

    const int NC = Hn / 32;    // 64

    // prologue: stage buffers 0 and 1
    bload(0);  aload(0, 0);  CPCOMMIT(); bstore(0);
    bload(32); aload(1, 32); CPCOMMIT(); bstore(1);

    for (int c = 0; c < NC; c++) {
        // ensure A-group for buffer c%3 is complete, then make all writes visible
        if (c + 1 < NC) { CPWAIT1(); } else { CPWAIT0(); }
        __syncthreads();
        bool pre = (c + 2 < NC);
        if (pre) {
            int kt2 = (c + 2) * 32;
            bload(kt2);                       // B LDGs in flight during compute
            aload((c + 2) % 3, kt2);          // A cp.async into buffer (c-1)%3 (free after sync)
            CPCOMMIT();
        }
        compute_tile<1, PLANE_A2>(sbase + (uint32_t)((c % 3) * BUF2_B), lane, warp_m, warp_n, acc);
        if (pre) bstore((c + 2) % 3);         // convert + STS after compute
    }

#pragma unroll
    for (int nt = 0; nt < 4; nt++) {
        int ncol_l = warp_n * 32 + nt * 8 + (lane & 3) * 2;
#pragma unroll
        for (int h = 0; h < 2; h++) {
            int grow = m0 + warp_m * 16 + (lane >> 2) + h * 8;
            float2 v = make_float2(acc[0][nt][h * 2 + 0], acc[0][nt][h * 2 + 1]);
            *reinterpret_cast<float2*>(g_y + (size_t)(e * Bn + grow) * On + n0 + ncol_l) = v;
        }
    }
}

// ---------------- combine (+ b2) — proven ----------------
__global__ void combine_kernel(const float* __restrict__ b2, float* __restrict__ out) {
    int idx = blockIdx.x * 256 + threadIdx.x;
    int b = idx >> 7;
    int o = (idx & 127) * 4;
    int p0 = g_pos[b * 2 + 0], p1 = g_pos[b * 2 + 1];
    float w0 = g_wk[b * 2 + 0], w1 = g_wk[b * 2 + 1];
    int e0 = p0 >> 10, e1 = p1 >> 10;
    float4 y0 = *reinterpret_cast<const float4*>(g_y + (size_t)p0 * On + o);
    float4 y1 = *reinterpret_cast<const float4*>(g_y + (size_t)p1 * On + o);
    float4 c0 = *reinterpret_cast<const float4*>(b2 + (size_t)e0 * On + o);
    float4 c1 = *reinterpret_cast<const float4*>(b2 + (size_t)e1 * On + o);
    float4 r;
    r.x = w0 * (y0.x + c0.x) + w1 * (y1.x + c1.x);
    r.y = w0 * (y0.y + c0.y) + w1 * (y1.y + c1.y);
    r.z = w0 * (y0.z + c0.z) + w1 * (y1.z + c1.z);
    r.w = w0 * (y0.w + c0.w) + w1 * (y1.w + c1.w);
    *reinterpret_cast<float4*>(out + (size_t)b * On + o) = r;
}

// ---------------- launch ----------------
extern "C" void kernel_launch(void* const* d_in, const int* in_sizes, int n_in,
                              void* d_out, int out_size) {
    const float* x  = (const float*)d_in[0];
    const float* Wg = (const float*)d_in[1];
    const float* bg = (const float*)d_in[2];
    const float* W1 = (const float*)d_in[3];
    const float* b1 = (const float*)d_in[4];
    const float* W2 = (const float*)d_in[5];
    const float* b2 = (const float*)d_in[6];
    float* out = (float*)d_out;

    zero_counts_kernel<<<1, 32>>>();
    gate_kernel<<<Bn / 8, 256>>>(x, Wg, bg);
    gemm1_mma<<<dim3(Hn / 64, Bn / 128, En), 256, GSMEM1>>>(x, W1, b1);
    gemm2_mma<<<dim3(On / 64, Bn / 64, En), 256, GSMEM2>>>(W2);
    combine_kernel<<<(Bn * On / 4) / 256, 256>>>(b2, out);
}